// round 1
// baseline (speedup 1.0000x reference)
#include <cuda_runtime.h>
#include <math.h>

// Problem constants
#define NTOK 512
#define DD   128
#define NN   (NTOK*NTOK)          // 262144 rows / per-channel matrix elems

// Scratch (static __device__ arrays — no allocation allowed)
// layouts:
//   g_left [h][k][i]   (h-major so einsum per-channel GEMM is contiguous)
//   g_right[h][k][j]
//   g_og   [h][i*512+j] (sigmoid(out-gate), transposed like the others)
//   g_mix  [d][i*512+j] (einsum result)
__device__ float g_left [33554432];
__device__ float g_right[33554432];
__device__ float g_og   [33554432];
__device__ float g_mix  [33554432];

// ---------------------------------------------------------------------------
// Kernel 1: LayerNorm + 5 projections (+bias, mask, sigmoid gating), writing
// left/right/ogate in transposed ([h][row]) layout.
// Block: 64 consecutive rows (all share the same n1=k since 64|512), 256 thr.
// GEMM phase: tx (0..15) -> rows (i), ty (0..15) -> cols (h), 4x4 micro-tile,
// column halves of 64 to keep register pressure low.
// ---------------------------------------------------------------------------
template<bool TWO>
__device__ __forceinline__ void proj_pass(
    const float (* __restrict__ xn_s)[64],
    float* __restrict__ wsA, float* __restrict__ wsB,
    const float* __restrict__ WA, const float* __restrict__ WB,
    int tid, int tx, int ty, int col0,
    float accA[4][4], float accB[4][4])
{
    const int dl = tid >> 4;
    const int cg = (tid & 15) * 4;
    #pragma unroll 1
    for (int dc = 0; dc < 128; dc += 16) {
        __syncthreads();   // protect previous reads of ws*
        *(float4*)&wsA[dl*64 + cg] = *(const float4*)&WA[(dc + dl)*DD + col0 + cg];
        if (TWO)
            *(float4*)&wsB[dl*64 + cg] = *(const float4*)&WB[(dc + dl)*DD + col0 + cg];
        __syncthreads();
        #pragma unroll
        for (int u = 0; u < 16; ++u) {
            float4 a  = *(const float4*)&xn_s[dc + u][4*tx];
            float4 bA = *(const float4*)&wsA[u*64 + 4*ty];
            float av[4]  = {a.x, a.y, a.z, a.w};
            float bAv[4] = {bA.x, bA.y, bA.z, bA.w};
            float bBv[4];
            if (TWO) {
                float4 bB = *(const float4*)&wsB[u*64 + 4*ty];
                bBv[0]=bB.x; bBv[1]=bB.y; bBv[2]=bB.z; bBv[3]=bB.w;
            }
            #pragma unroll
            for (int cc = 0; cc < 4; ++cc) {
                #pragma unroll
                for (int rr = 0; rr < 4; ++rr) {
                    accA[cc][rr] += av[rr] * bAv[cc];
                    if (TWO) accB[cc][rr] += av[rr] * bBv[cc];
                }
            }
        }
    }
    __syncthreads();
}

__device__ __forceinline__ float sigmoidf_(float z)
{
    return 1.f / (1.f + expf(-z));
}

__global__ __launch_bounds__(256) void ln_proj_kernel(
    const float* __restrict__ x,   const float* __restrict__ msk,
    const float* __restrict__ nsc, const float* __restrict__ nbi,
    const float* __restrict__ Wl,  const float* __restrict__ bl,
    const float* __restrict__ Wr,  const float* __restrict__ br,
    const float* __restrict__ Wlg, const float* __restrict__ blg,
    const float* __restrict__ Wrg, const float* __restrict__ brg,
    const float* __restrict__ Wog, const float* __restrict__ bog)
{
    __shared__ float xn_s[128][64];   // [d][row], transposed for f4 row loads
    __shared__ float w_s[2][16][64];

    const int tid = threadIdx.x;
    const int r0  = blockIdx.x * 64;  // global row base
    const int k   = r0 >> 9;          // n1 (constant in block)
    const int ib  = r0 & 511;         // n2 base

    // ---- LayerNorm: 4 threads per row, 32 elems each ----
    {
        const int row = tid >> 2, sub = tid & 3;
        const float4* xr = reinterpret_cast<const float4*>(
                               x + (size_t)(r0 + row) * DD) + sub * 8;
        float4 v[8];
        float s = 0.f, ss = 0.f;
        #pragma unroll
        for (int q = 0; q < 8; ++q) {
            v[q] = xr[q];
            s  += v[q].x + v[q].y + v[q].z + v[q].w;
            ss += v[q].x*v[q].x + v[q].y*v[q].y + v[q].z*v[q].z + v[q].w*v[q].w;
        }
        s  += __shfl_xor_sync(0xffffffffu, s, 1);
        ss += __shfl_xor_sync(0xffffffffu, ss, 1);
        s  += __shfl_xor_sync(0xffffffffu, s, 2);
        ss += __shfl_xor_sync(0xffffffffu, ss, 2);
        const float mu   = s * (1.f/128.f);
        const float var  = ss * (1.f/128.f) - mu*mu;
        const float rstd = rsqrtf(var + 1e-6f);
        #pragma unroll
        for (int q = 0; q < 8; ++q) {
            const int d = sub*32 + q*4;
            xn_s[d+0][row] = (v[q].x - mu)*rstd*nsc[d+0] + nbi[d+0];
            xn_s[d+1][row] = (v[q].y - mu)*rstd*nsc[d+1] + nbi[d+1];
            xn_s[d+2][row] = (v[q].z - mu)*rstd*nsc[d+2] + nbi[d+2];
            xn_s[d+3][row] = (v[q].w - mu)*rstd*nsc[d+3] + nbi[d+3];
        }
    }
    __syncthreads();

    const int tx = tid & 15, ty = tid >> 4;
    const float mk = msk[k];
    float maskv[4];
    #pragma unroll
    for (int rr = 0; rr < 4; ++rr) maskv[rr] = mk * msk[ib + 4*tx + rr];

    float* wsA = &w_s[0][0][0];
    float* wsB = &w_s[1][0][0];

    // ---- pass 1: left & left-gate ----
    #pragma unroll 1
    for (int half = 0; half < 2; ++half) {
        const int col0 = half * 64;
        float accA[4][4] = {}, accB[4][4] = {};
        proj_pass<true>(xn_s, wsA, wsB, Wl, Wlg, tid, tx, ty, col0, accA, accB);
        #pragma unroll
        for (int cc = 0; cc < 4; ++cc) {
            const int c = col0 + 4*ty + cc;
            const float ba = bl[c], bg = blg[c];
            float4 o;
            o.x = (accA[cc][0] + ba) * maskv[0] * sigmoidf_(accB[cc][0] + bg);
            o.y = (accA[cc][1] + ba) * maskv[1] * sigmoidf_(accB[cc][1] + bg);
            o.z = (accA[cc][2] + ba) * maskv[2] * sigmoidf_(accB[cc][2] + bg);
            o.w = (accA[cc][3] + ba) * maskv[3] * sigmoidf_(accB[cc][3] + bg);
            *(float4*)&g_left[(size_t)c*NN + r0 + 4*tx] = o;
        }
    }

    // ---- pass 2: right & right-gate ----
    #pragma unroll 1
    for (int half = 0; half < 2; ++half) {
        const int col0 = half * 64;
        float accA[4][4] = {}, accB[4][4] = {};
        proj_pass<true>(xn_s, wsA, wsB, Wr, Wrg, tid, tx, ty, col0, accA, accB);
        #pragma unroll
        for (int cc = 0; cc < 4; ++cc) {
            const int c = col0 + 4*ty + cc;
            const float ba = br[c], bg = brg[c];
            float4 o;
            o.x = (accA[cc][0] + ba) * maskv[0] * sigmoidf_(accB[cc][0] + bg);
            o.y = (accA[cc][1] + ba) * maskv[1] * sigmoidf_(accB[cc][1] + bg);
            o.z = (accA[cc][2] + ba) * maskv[2] * sigmoidf_(accB[cc][2] + bg);
            o.w = (accA[cc][3] + ba) * maskv[3] * sigmoidf_(accB[cc][3] + bg);
            *(float4*)&g_right[(size_t)c*NN + r0 + 4*tx] = o;
        }
    }

    // ---- pass 3: out-gate ----
    #pragma unroll 1
    for (int half = 0; half < 2; ++half) {
        const int col0 = half * 64;
        float accA[4][4] = {}, accB[4][4] = {};
        proj_pass<false>(xn_s, wsA, wsB, Wog, (const float*)0, tid, tx, ty, col0, accA, accB);
        #pragma unroll
        for (int cc = 0; cc < 4; ++cc) {
            const int c = col0 + 4*ty + cc;
            const float ba = bog[c];
            float4 o;
            o.x = sigmoidf_(accA[cc][0] + ba);
            o.y = sigmoidf_(accA[cc][1] + ba);
            o.z = sigmoidf_(accA[cc][2] + ba);
            o.w = sigmoidf_(accA[cc][3] + ba);
            *(float4*)&g_og[(size_t)c*NN + r0 + 4*tx] = o;
        }
    }
}

// ---------------------------------------------------------------------------
// Kernel 2: einsum 'bkid,bkjd->bijd' as 128 per-channel GEMMs
// C_d[i][j] = sum_k L_d[k][i] * R_d[k][j]; 64x64 block tile, 4x4 micro-tile.
// grid = (64 tiles, 128 channels)
// ---------------------------------------------------------------------------
__global__ __launch_bounds__(256) void einsum_kernel()
{
    const int d  = blockIdx.y;
    const int it = (blockIdx.x >> 3) * 64;
    const int jt = (blockIdx.x & 7) * 64;
    const float* __restrict__ A = g_left  + (size_t)d * NN;  // [k][i]
    const float* __restrict__ B = g_right + (size_t)d * NN;  // [k][j]

    __shared__ float As[16][64];
    __shared__ float Bs[16][64];

    const int tid = threadIdx.x;
    const int tx = tid & 15, ty = tid >> 4;
    const int kl = tid >> 4, g4 = (tid & 15) * 4;

    float acc[4][4] = {};

    #pragma unroll 1
    for (int kc = 0; kc < 512; kc += 16) {
        *(float4*)&As[kl][g4] = *(const float4*)&A[(size_t)(kc + kl)*512 + it + g4];
        *(float4*)&Bs[kl][g4] = *(const float4*)&B[(size_t)(kc + kl)*512 + jt + g4];
        __syncthreads();
        #pragma unroll
        for (int kk = 0; kk < 16; ++kk) {
            float4 a = *(const float4*)&As[kk][4*ty];
            float4 b = *(const float4*)&Bs[kk][4*tx];
            float av[4] = {a.x, a.y, a.z, a.w};
            float bv[4] = {b.x, b.y, b.z, b.w};
            #pragma unroll
            for (int ii = 0; ii < 4; ++ii)
                #pragma unroll
                for (int jj = 0; jj < 4; ++jj)
                    acc[ii][jj] += av[ii] * bv[jj];
        }
        __syncthreads();
    }

    #pragma unroll
    for (int ii = 0; ii < 4; ++ii) {
        float4 o = {acc[ii][0], acc[ii][1], acc[ii][2], acc[ii][3]};
        *(float4*)&g_mix[(size_t)d*NN + (size_t)(it + 4*ty + ii)*512 + jt + 4*tx] = o;
    }
}

// ---------------------------------------------------------------------------
// Kernel 3: out-LayerNorm (over d) * out_gate, then @ W_out + b_out.
// Block: 64 consecutive output rows (r = i*512+j). Reads g_mix/g_og coalesced
// along r (d-major layout), GEMM 64x128x128 out of smem.
// ---------------------------------------------------------------------------
__global__ __launch_bounds__(256) void out_kernel(
    const float* __restrict__ gs, const float* __restrict__ gb,
    const float* __restrict__ Wout, const float* __restrict__ bout,
    float* __restrict__ out)
{
    __shared__ float gg_s[128][64];   // [d][row]
    __shared__ float w_s[16][128];
    __shared__ float red[2][4][64];

    const int tid = threadIdx.x;
    const int r0  = blockIdx.x * 64;
    const int rl  = tid & 63;
    const int dg  = tid >> 6;         // 0..3, each covers 32 d's

    // pass 1: sum / sumsq over d (coalesced along r)
    float s = 0.f, q = 0.f;
    #pragma unroll 4
    for (int dd = dg*32; dd < dg*32 + 32; ++dd) {
        float v = g_mix[(size_t)dd*NN + r0 + rl];
        s += v; q += v*v;
    }
    red[0][dg][rl] = s; red[1][dg][rl] = q;
    __syncthreads();
    const float S = red[0][0][rl] + red[0][1][rl] + red[0][2][rl] + red[0][3][rl];
    const float Q = red[1][0][rl] + red[1][1][rl] + red[1][2][rl] + red[1][3][rl];
    const float mu   = S * (1.f/128.f);
    const float rstd = rsqrtf(Q * (1.f/128.f) - mu*mu + 1e-6f);

    // pass 2: normalized * gate into smem
    #pragma unroll 4
    for (int dd = dg*32; dd < dg*32 + 32; ++dd) {
        float v = g_mix[(size_t)dd*NN + r0 + rl];
        float o = g_og [(size_t)dd*NN + r0 + rl];
        gg_s[dd][rl] = ((v - mu)*rstd*gs[dd] + gb[dd]) * o;
    }
    __syncthreads();

    // GEMM: out[row][c] = sum_d gg[d][row] * Wout[d][c] + bout[c]
    const int tx = tid & 15, ty = tid >> 4;   // tx->8 cols, ty->4 rows
    float acc[4][8] = {};
    #pragma unroll 1
    for (int dc = 0; dc < 128; dc += 16) {
        const int dl = tid >> 4, cg = (tid & 15) * 8;
        *(float4*)&w_s[dl][cg]     = *(const float4*)&Wout[(dc + dl)*DD + cg];
        *(float4*)&w_s[dl][cg + 4] = *(const float4*)&Wout[(dc + dl)*DD + cg + 4];
        __syncthreads();
        #pragma unroll
        for (int u = 0; u < 16; ++u) {
            float4 a  = *(const float4*)&gg_s[dc + u][4*ty];
            float4 b0 = *(const float4*)&w_s[u][8*tx];
            float4 b1 = *(const float4*)&w_s[u][8*tx + 4];
            float av[4] = {a.x, a.y, a.z, a.w};
            float bv[8] = {b0.x, b0.y, b0.z, b0.w, b1.x, b1.y, b1.z, b1.w};
            #pragma unroll
            for (int ii = 0; ii < 4; ++ii)
                #pragma unroll
                for (int cc = 0; cc < 8; ++cc)
                    acc[ii][cc] += av[ii] * bv[cc];
        }
        __syncthreads();
    }

    const float4 bo0 = *(const float4*)&bout[8*tx];
    const float4 bo1 = *(const float4*)&bout[8*tx + 4];
    #pragma unroll
    for (int ii = 0; ii < 4; ++ii) {
        const size_t base = (size_t)(r0 + 4*ty + ii)*DD + 8*tx;
        float4 o0 = {acc[ii][0]+bo0.x, acc[ii][1]+bo0.y, acc[ii][2]+bo0.z, acc[ii][3]+bo0.w};
        float4 o1 = {acc[ii][4]+bo1.x, acc[ii][5]+bo1.y, acc[ii][6]+bo1.z, acc[ii][7]+bo1.w};
        *(float4*)&out[base]     = o0;
        *(float4*)&out[base + 4] = o1;
    }
}

// ---------------------------------------------------------------------------
extern "C" void kernel_launch(void* const* d_in, const int* in_sizes, int n_in,
                              void* d_out, int out_size)
{
    const float* x    = (const float*)d_in[0];
    const float* mskp = (const float*)d_in[1];
    const float* nsc  = (const float*)d_in[2];
    const float* nbi  = (const float*)d_in[3];
    const float* Wl   = (const float*)d_in[4];
    const float* bl   = (const float*)d_in[5];
    const float* Wr   = (const float*)d_in[6];
    const float* br   = (const float*)d_in[7];
    const float* Wlg  = (const float*)d_in[8];
    const float* blg  = (const float*)d_in[9];
    const float* Wrg  = (const float*)d_in[10];
    const float* brg  = (const float*)d_in[11];
    const float* Wog  = (const float*)d_in[12];
    const float* bog  = (const float*)d_in[13];
    const float* gs   = (const float*)d_in[14];
    const float* gb   = (const float*)d_in[15];
    const float* Wout = (const float*)d_in[16];
    const float* bout = (const float*)d_in[17];
    float* out = (float*)d_out;

    ln_proj_kernel<<<NN/64, 256>>>(x, mskp, nsc, nbi, Wl, bl, Wr, br,
                                   Wlg, blg, Wrg, brg, Wog, bog);
    einsum_kernel<<<dim3(64, 128), 256>>>();
    out_kernel<<<NN/64, 256>>>(gs, gb, Wout, bout, out);
}

// round 3
// speedup vs baseline: 1.2445x; 1.2445x over previous
#include <cuda_runtime.h>
#include <cuda_bf16.h>
#include <math.h>
#include <stdint.h>

// Problem constants
#define NTOK 512
#define DD   128
#define NN   (NTOK*NTOK)

// Scratch (static __device__ arrays — no allocation allowed)
// layouts:
//   g_lh/g_ll [c][i*512+k]  left  hi/lo bf16  (K-major for MMA A)
//   g_rh/g_rl [c][j*512+k]  right hi/lo bf16  (K-major for MMA B)
//   g_og      [c][j*512+i]  sigmoid(out-gate) f32
//   g_mix     [d][j*512+i]  einsum result f32 (transposed)
__device__ __nv_bfloat16 g_lh[33554432];
__device__ __nv_bfloat16 g_ll[33554432];
__device__ __nv_bfloat16 g_rh[33554432];
__device__ __nv_bfloat16 g_rl[33554432];
__device__ float         g_og [33554432];
__device__ float         g_mix[33554432];

// ---------------------------------------------------------------------------
// helpers
// ---------------------------------------------------------------------------
__device__ __forceinline__ uint32_t smem_u32(const void* p) {
    uint32_t a;
    asm("{ .reg .u64 t; cvta.to.shared.u64 t, %1; cvt.u32.u64 %0, t; }"
        : "=r"(a) : "l"(p));
    return a;
}

__device__ __forceinline__ void ldm4(uint32_t r[4], uint32_t addr) {
    asm volatile("ldmatrix.sync.aligned.m8n8.x4.shared.b16 {%0,%1,%2,%3}, [%4];"
                 : "=r"(r[0]), "=r"(r[1]), "=r"(r[2]), "=r"(r[3]) : "r"(addr));
}

__device__ __forceinline__ void mma_bf16(float acc[4], const uint32_t a[4],
                                         uint32_t b0, uint32_t b1) {
    asm volatile(
        "mma.sync.aligned.m16n8k16.row.col.f32.bf16.bf16.f32 "
        "{%0,%1,%2,%3}, {%4,%5,%6,%7}, {%8,%9}, {%0,%1,%2,%3};"
        : "+f"(acc[0]), "+f"(acc[1]), "+f"(acc[2]), "+f"(acc[3])
        : "r"(a[0]), "r"(a[1]), "r"(a[2]), "r"(a[3]), "r"(b0), "r"(b1));
}

__device__ __forceinline__ float sigmoidf_(float z) {
    return 1.f / (1.f + expf(-z));
}

__device__ __forceinline__ void split_bf(float v, __nv_bfloat16& h, __nv_bfloat16& l) {
    h = __float2bfloat16(v);
    l = __float2bfloat16(v - __bfloat162float(h));
}

// ---------------------------------------------------------------------------
// Kernel 1: LayerNorm + 5 projections (+bias, mask, sigmoid gating).
// Block covers rows (n1, n2) with n1 in [n1b, n1b+64) contiguous, n2 fixed.
// For left/right that means k contiguous -> coalesced K-major bf16 stores.
// ---------------------------------------------------------------------------
template<bool TWO>
__device__ __forceinline__ void proj_pass(
    const float (* __restrict__ xn_s)[64],
    float* __restrict__ wsA, float* __restrict__ wsB,
    const float* __restrict__ WA, const float* __restrict__ WB,
    int tid, int tx, int ty, int col0,
    float accA[4][4], float accB[4][4])
{
    const int dl = tid >> 4;
    const int cg = (tid & 15) * 4;
    #pragma unroll 1
    for (int dc = 0; dc < 128; dc += 16) {
        __syncthreads();
        *(float4*)&wsA[dl*64 + cg] = *(const float4*)&WA[(dc + dl)*DD + col0 + cg];
        if (TWO)
            *(float4*)&wsB[dl*64 + cg] = *(const float4*)&WB[(dc + dl)*DD + col0 + cg];
        __syncthreads();
        #pragma unroll
        for (int u = 0; u < 16; ++u) {
            float4 a  = *(const float4*)&xn_s[dc + u][4*tx];
            float4 bA = *(const float4*)&wsA[u*64 + 4*ty];
            float av[4]  = {a.x, a.y, a.z, a.w};
            float bAv[4] = {bA.x, bA.y, bA.z, bA.w};
            float bBv[4];
            if (TWO) {
                float4 bB = *(const float4*)&wsB[u*64 + 4*ty];
                bBv[0]=bB.x; bBv[1]=bB.y; bBv[2]=bB.z; bBv[3]=bB.w;
            }
            #pragma unroll
            for (int cc = 0; cc < 4; ++cc) {
                #pragma unroll
                for (int rr = 0; rr < 4; ++rr) {
                    accA[cc][rr] += av[rr] * bAv[cc];
                    if (TWO) accB[cc][rr] += av[rr] * bBv[cc];
                }
            }
        }
    }
    __syncthreads();
}

__global__ __launch_bounds__(256) void ln_proj_kernel(
    const float* __restrict__ x,   const float* __restrict__ msk,
    const float* __restrict__ nsc, const float* __restrict__ nbi,
    const float* __restrict__ Wl,  const float* __restrict__ bl,
    const float* __restrict__ Wr,  const float* __restrict__ br,
    const float* __restrict__ Wlg, const float* __restrict__ blg,
    const float* __restrict__ Wrg, const float* __restrict__ brg,
    const float* __restrict__ Wog, const float* __restrict__ bog)
{
    __shared__ float xn_s[128][64];   // [d][row_local]
    __shared__ float w_s[2][16][64];

    const int tid = threadIdx.x;
    const int n2  = blockIdx.x & 511;        // fixed second index (i or j)
    const int n1b = (blockIdx.x >> 9) * 64;  // base of contiguous n1 (=k)

    // ---- LayerNorm: 4 threads per row, 32 elems each ----
    {
        const int row = tid >> 2, sub = tid & 3;
        const float4* xr = reinterpret_cast<const float4*>(
                               x + ((size_t)(n1b + row) * 512 + n2) * DD) + sub * 8;
        float4 v[8];
        float s = 0.f, ss = 0.f;
        #pragma unroll
        for (int q = 0; q < 8; ++q) {
            v[q] = xr[q];
            s  += v[q].x + v[q].y + v[q].z + v[q].w;
            ss += v[q].x*v[q].x + v[q].y*v[q].y + v[q].z*v[q].z + v[q].w*v[q].w;
        }
        s  += __shfl_xor_sync(0xffffffffu, s, 1);
        ss += __shfl_xor_sync(0xffffffffu, ss, 1);
        s  += __shfl_xor_sync(0xffffffffu, s, 2);
        ss += __shfl_xor_sync(0xffffffffu, ss, 2);
        const float mu   = s * (1.f/128.f);
        const float var  = ss * (1.f/128.f) - mu*mu;
        const float rstd = rsqrtf(var + 1e-6f);
        #pragma unroll
        for (int q = 0; q < 8; ++q) {
            const int d = sub*32 + q*4;
            xn_s[d+0][row] = (v[q].x - mu)*rstd*nsc[d+0] + nbi[d+0];
            xn_s[d+1][row] = (v[q].y - mu)*rstd*nsc[d+1] + nbi[d+1];
            xn_s[d+2][row] = (v[q].z - mu)*rstd*nsc[d+2] + nbi[d+2];
            xn_s[d+3][row] = (v[q].w - mu)*rstd*nsc[d+3] + nbi[d+3];
        }
    }
    __syncthreads();

    const int tx = tid & 15, ty = tid >> 4;
    const float m2 = msk[n2];
    float maskv[4];
    #pragma unroll
    for (int rr = 0; rr < 4; ++rr) maskv[rr] = m2 * msk[n1b + 4*tx + rr];

    float* wsA = &w_s[0][0][0];
    float* wsB = &w_s[1][0][0];

    // ---- pass 1: left & left-gate ----
    #pragma unroll 1
    for (int half = 0; half < 2; ++half) {
        const int col0 = half * 64;
        float accA[4][4] = {}, accB[4][4] = {};
        proj_pass<true>(xn_s, wsA, wsB, Wl, Wlg, tid, tx, ty, col0, accA, accB);
        #pragma unroll
        for (int cc = 0; cc < 4; ++cc) {
            const int c = col0 + 4*ty + cc;
            const float ba = bl[c], bg = blg[c];
            __align__(8) __nv_bfloat16 h[4], l[4];
            #pragma unroll
            for (int rr = 0; rr < 4; ++rr) {
                float o = (accA[cc][rr] + ba) * maskv[rr] * sigmoidf_(accB[cc][rr] + bg);
                split_bf(o, h[rr], l[rr]);
            }
            const size_t idx = (size_t)c*NN + (size_t)n2*512 + n1b + 4*tx;
            *(uint2*)&g_lh[idx] = *(uint2*)h;
            *(uint2*)&g_ll[idx] = *(uint2*)l;
        }
    }

    // ---- pass 2: right & right-gate ----
    #pragma unroll 1
    for (int half = 0; half < 2; ++half) {
        const int col0 = half * 64;
        float accA[4][4] = {}, accB[4][4] = {};
        proj_pass<true>(xn_s, wsA, wsB, Wr, Wrg, tid, tx, ty, col0, accA, accB);
        #pragma unroll
        for (int cc = 0; cc < 4; ++cc) {
            const int c = col0 + 4*ty + cc;
            const float ba = br[c], bg = brg[c];
            __align__(8) __nv_bfloat16 h[4], l[4];
            #pragma unroll
            for (int rr = 0; rr < 4; ++rr) {
                float o = (accA[cc][rr] + ba) * maskv[rr] * sigmoidf_(accB[cc][rr] + bg);
                split_bf(o, h[rr], l[rr]);
            }
            const size_t idx = (size_t)c*NN + (size_t)n2*512 + n1b + 4*tx;
            *(uint2*)&g_rh[idx] = *(uint2*)h;
            *(uint2*)&g_rl[idx] = *(uint2*)l;
        }
    }

    // ---- pass 3: out-gate (row (n1,n2) -> (i=n1, j=n2); store [c][j*512+i]) ----
    #pragma unroll 1
    for (int half = 0; half < 2; ++half) {
        const int col0 = half * 64;
        float accA[4][4] = {}, accB[4][4] = {};
        proj_pass<false>(xn_s, wsA, wsB, Wog, (const float*)0, tid, tx, ty, col0, accA, accB);
        #pragma unroll
        for (int cc = 0; cc < 4; ++cc) {
            const int c = col0 + 4*ty + cc;
            const float ba = bog[c];
            float4 o;
            o.x = sigmoidf_(accA[cc][0] + ba);
            o.y = sigmoidf_(accA[cc][1] + ba);
            o.z = sigmoidf_(accA[cc][2] + ba);
            o.w = sigmoidf_(accA[cc][3] + ba);
            *(float4*)&g_og[(size_t)c*NN + (size_t)n2*512 + n1b + 4*tx] = o;
        }
    }
}

// ---------------------------------------------------------------------------
// Kernel 2: einsum 'bkid,bkjd->bijd' via mma.sync bf16 (hi/lo split, 3 MMAs).
// Per CTA: one channel d, one 128x128 tile. 8 warps (4 m x 2 n), warp tile
// 32x64. K=512 in 16 chunks of 32, double-buffered SMEM (80B row stride ->
// conflict-free ldmatrix). Output transposed to g_mix[d][j*512+i] via SMEM.
// SMEM per stage: 4 arrays (AH,AL,BH,BL) x 128 rows x 80B = 40960B.
// ---------------------------------------------------------------------------
#define EIN_STAGE  40960
#define EIN_SMEM   (2*EIN_STAGE)   // 81920; epilogue reuses 128*129*4=66048

__global__ __launch_bounds__(256) void einsum_mma_kernel()
{
    extern __shared__ __align__(16) char esm[];
    const int tid  = threadIdx.x;
    const int lane = tid & 31;
    const int wid  = tid >> 5;
    const int d    = blockIdx.y;
    const int i0   = (blockIdx.x & 3) * 128;
    const int j0   = (blockIdx.x >> 2) * 128;
    const uint32_t sbm = smem_u32(esm);

    const __nv_bfloat16* __restrict__ pAH = g_lh + (size_t)d*NN;
    const __nv_bfloat16* __restrict__ pAL = g_ll + (size_t)d*NN;
    const __nv_bfloat16* __restrict__ pBH = g_rh + (size_t)d*NN;
    const __nv_bfloat16* __restrict__ pBL = g_rl + (size_t)d*NN;

    // ---- per-thread global/smem mapping for chunk loads ----
    // each chunk: 4 arrays x 128 rows x 64B; 256 thr x 8 iters x 16B
    const __nv_bfloat16* gptr[8];
    uint32_t soff[8];
    #pragma unroll
    for (int it = 0; it < 8; ++it) {
        const int idx = it*256 + tid;
        const int arr = idx >> 9;           // 0:AH 1:AL 2:BH 3:BL
        const int rem = idx & 511;
        const int row = rem >> 2;
        const int seg = rem & 3;
        const __nv_bfloat16* src =
            (arr == 0) ? pAH : (arr == 1) ? pAL : (arr == 2) ? pBH : pBL;
        const int r0 = (arr < 2) ? i0 : j0;
        gptr[it] = src + (size_t)(r0 + row)*512 + seg*8;
        soff[it] = (uint32_t)(arr*10240 + row*80 + seg*16);
    }

    // ---- ldmatrix per-lane addresses (within a stage) ----
    const int g = lane >> 3, r = lane & 7;
    const int wm = (wid & 3) * 32;
    const int wn = (wid >> 2) * 64;
    // A frag (m16k16): row += (g&1)*8, k += (g>>1)*8
    uint32_t aoff[2][2];   // [split][mi]
    #pragma unroll
    for (int mi = 0; mi < 2; ++mi) {
        const uint32_t base = (uint32_t)((wm + mi*16 + r + (g&1)*8)*80 + ((g>>1)*8)*2);
        aoff[0][mi] = sbm + base;            // AH at arr 0
        aoff[1][mi] = sbm + 10240 + base;    // AL
    }
    // B frag pairs (two n8k16 tiles per x4): n += (g>>1)*8, k += (g&1)*8
    uint32_t boff[2][4];   // [split][pair]
    #pragma unroll
    for (int p = 0; p < 4; ++p) {
        const uint32_t base = (uint32_t)((wn + p*16 + r + (g>>1)*8)*80 + ((g&1)*8)*2);
        boff[0][p] = sbm + 20480 + base;     // BH
        boff[1][p] = sbm + 30720 + base;     // BL
    }

    float acc[2][8][4] = {};
    uint4 v[8];

    // prefetch chunk 0 -> stage 0
    #pragma unroll
    for (int it = 0; it < 8; ++it) v[it] = *(const uint4*)(gptr[it]);
    #pragma unroll
    for (int it = 0; it < 8; ++it) *(uint4*)(esm + soff[it]) = v[it];
    __syncthreads();

    #pragma unroll 1
    for (int kc = 0; kc < 16; ++kc) {
        const uint32_t stg = (uint32_t)(kc & 1) * EIN_STAGE;
        if (kc < 15) {
            const int kb = (kc + 1) * 32;
            #pragma unroll
            for (int it = 0; it < 8; ++it)
                v[it] = *(const uint4*)(gptr[it] + kb);
        }
        #pragma unroll
        for (int ks2 = 0; ks2 < 2; ++ks2) {
            const uint32_t off = stg + (uint32_t)ks2 * 32;   // k16 step = 32B
            uint32_t AH[2][4], AL[2][4], BH[4][4], BL[4][4];
            #pragma unroll
            for (int mi = 0; mi < 2; ++mi) {
                ldm4(AH[mi], aoff[0][mi] + off);
                ldm4(AL[mi], aoff[1][mi] + off);
            }
            #pragma unroll
            for (int p = 0; p < 4; ++p) {
                ldm4(BH[p], boff[0][p] + off);
                ldm4(BL[p], boff[1][p] + off);
            }
            #pragma unroll
            for (int mi = 0; mi < 2; ++mi)
                #pragma unroll
                for (int ni = 0; ni < 8; ++ni) {
                    const int p = ni >> 1, h = (ni & 1) * 2;
                    mma_bf16(acc[mi][ni], AH[mi], BH[p][h], BH[p][h+1]);
                    mma_bf16(acc[mi][ni], AH[mi], BL[p][h], BL[p][h+1]);
                    mma_bf16(acc[mi][ni], AL[mi], BH[p][h], BH[p][h+1]);
                }
        }
        if (kc < 15) {
            const uint32_t nstg = (uint32_t)((kc + 1) & 1) * EIN_STAGE;
            #pragma unroll
            for (int it = 0; it < 8; ++it)
                *(uint4*)(esm + nstg + soff[it]) = v[it];
            __syncthreads();
        }
    }

    // ---- epilogue: frag -> smem [j][i] (stride 129) -> coalesced stores ----
    __syncthreads();
    float* smT = (float*)esm;
    #pragma unroll
    for (int mi = 0; mi < 2; ++mi)
        #pragma unroll
        for (int ni = 0; ni < 8; ++ni) {
            const int m = wm + mi*16 + (lane >> 2);
            const int j = wn + ni*8 + (lane & 3)*2;
            smT[(j  )*129 + m    ] = acc[mi][ni][0];
            smT[(j+1)*129 + m    ] = acc[mi][ni][1];
            smT[(j  )*129 + m + 8] = acc[mi][ni][2];
            smT[(j+1)*129 + m + 8] = acc[mi][ni][3];
        }
    __syncthreads();

    float* gm = g_mix + (size_t)d * NN;
    #pragma unroll
    for (int it = 0; it < 16; ++it) {
        const int idx = it*256 + tid;
        const int j = idx >> 5, c4 = idx & 31;
        float4 o;
        o.x = smT[j*129 + c4*4 + 0];
        o.y = smT[j*129 + c4*4 + 1];
        o.z = smT[j*129 + c4*4 + 2];
        o.w = smT[j*129 + c4*4 + 3];
        *reinterpret_cast<float4*>(gm + (size_t)(j0 + j)*512 + i0 + c4*4) = o;
    }
}

// ---------------------------------------------------------------------------
// Kernel 3: out-LayerNorm (over d) * out_gate, then @ W_out + b_out.
// Rows rt = j*512+i (fixed j per block); g_mix/g_og read coalesced; final
// stores staged via SMEM so each (i,j) row's 128 channels are contiguous.
// ---------------------------------------------------------------------------
__global__ __launch_bounds__(256) void out_kernel(
    const float* __restrict__ gs, const float* __restrict__ gb,
    const float* __restrict__ Wout, const float* __restrict__ bout,
    float* __restrict__ out)
{
    __shared__ float gg_s[128][64];   // [d][row_local] ; reused as out_s[64][128]
    __shared__ float w_s[16][128];
    __shared__ float red[2][4][64];

    const int tid = threadIdx.x;
    const int rt0 = blockIdx.x * 64;      // rt = j*512 + i
    const int j   = rt0 >> 9;
    const int ibase = rt0 & 511;
    const int rl  = tid & 63;
    const int dg  = tid >> 6;

    float s = 0.f, q = 0.f;
    #pragma unroll 4
    for (int dd = dg*32; dd < dg*32 + 32; ++dd) {
        float v = g_mix[(size_t)dd*NN + rt0 + rl];
        s += v; q += v*v;
    }
    red[0][dg][rl] = s; red[1][dg][rl] = q;
    __syncthreads();
    const float S = red[0][0][rl] + red[0][1][rl] + red[0][2][rl] + red[0][3][rl];
    const float Q = red[1][0][rl] + red[1][1][rl] + red[1][2][rl] + red[1][3][rl];
    const float mu   = S * (1.f/128.f);
    const float rstd = rsqrtf(Q * (1.f/128.f) - mu*mu + 1e-6f);

    #pragma unroll 4
    for (int dd = dg*32; dd < dg*32 + 32; ++dd) {
        float v = g_mix[(size_t)dd*NN + rt0 + rl];
        float o = g_og [(size_t)dd*NN + rt0 + rl];
        gg_s[dd][rl] = ((v - mu)*rstd*gs[dd] + gb[dd]) * o;
    }
    __syncthreads();

    const int tx = tid & 15, ty = tid >> 4;
    float acc[4][8] = {};
    #pragma unroll 1
    for (int dc = 0; dc < 128; dc += 16) {
        const int dl = tid >> 4, cg = (tid & 15) * 8;
        *(float4*)&w_s[dl][cg]     = *(const float4*)&Wout[(dc + dl)*DD + cg];
        *(float4*)&w_s[dl][cg + 4] = *(const float4*)&Wout[(dc + dl)*DD + cg + 4];
        __syncthreads();
        #pragma unroll
        for (int u = 0; u < 16; ++u) {
            float4 a  = *(const float4*)&gg_s[dc + u][4*ty];
            float4 b0 = *(const float4*)&w_s[u][8*tx];
            float4 b1 = *(const float4*)&w_s[u][8*tx + 4];
            float av[4] = {a.x, a.y, a.z, a.w};
            float bv[8] = {b0.x, b0.y, b0.z, b0.w, b1.x, b1.y, b1.z, b1.w};
            #pragma unroll
            for (int ii = 0; ii < 4; ++ii)
                #pragma unroll
                for (int cc = 0; cc < 8; ++cc)
                    acc[ii][cc] += av[ii] * bv[cc];
        }
        __syncthreads();
    }

    float* sbuf = &gg_s[0][0];   // now [64][128]
    const float4 bo0 = *(const float4*)&bout[8*tx];
    const float4 bo1 = *(const float4*)&bout[8*tx + 4];
    #pragma unroll
    for (int ii = 0; ii < 4; ++ii) {
        float* rowp = sbuf + (4*ty + ii)*128 + 8*tx;
        rowp[0] = acc[ii][0] + bo0.x;
        rowp[1] = acc[ii][1] + bo0.y;
        rowp[2] = acc[ii][2] + bo0.z;
        rowp[3] = acc[ii][3] + bo0.w;
        rowp[4] = acc[ii][4] + bo1.x;
        rowp[5] = acc[ii][5] + bo1.y;
        rowp[6] = acc[ii][6] + bo1.z;
        rowp[7] = acc[ii][7] + bo1.w;
    }
    __syncthreads();
    #pragma unroll
    for (int it = 0; it < 8; ++it) {
        const int idx = it * 256 + tid;       // 64 rows x 32 f4
        const int row = idx >> 5, c4 = idx & 31;
        float4 v = *reinterpret_cast<float4*>(&sbuf[row*128 + c4*4]);
        *reinterpret_cast<float4*>(
            out + ((size_t)(ibase + row)*512 + j)*DD + c4*4) = v;
    }
}

// ---------------------------------------------------------------------------
extern "C" void kernel_launch(void* const* d_in, const int* in_sizes, int n_in,
                              void* d_out, int out_size)
{
    const float* x    = (const float*)d_in[0];
    const float* mskp = (const float*)d_in[1];
    const float* nsc  = (const float*)d_in[2];
    const float* nbi  = (const float*)d_in[3];
    const float* Wl   = (const float*)d_in[4];
    const float* bl   = (const float*)d_in[5];
    const float* Wr   = (const float*)d_in[6];
    const float* br   = (const float*)d_in[7];
    const float* Wlg  = (const float*)d_in[8];
    const float* blg  = (const float*)d_in[9];
    const float* Wrg  = (const float*)d_in[10];
    const float* brg  = (const float*)d_in[11];
    const float* Wog  = (const float*)d_in[12];
    const float* bog  = (const float*)d_in[13];
    const float* gs   = (const float*)d_in[14];
    const float* gb   = (const float*)d_in[15];
    const float* Wout = (const float*)d_in[16];
    const float* bout = (const float*)d_in[17];
    float* out = (float*)d_out;

    static int smem_set = 0;
    if (!smem_set) {
        cudaFuncSetAttribute(einsum_mma_kernel,
                             cudaFuncAttributeMaxDynamicSharedMemorySize,
                             EIN_SMEM);
        smem_set = 1;
    }

    ln_proj_kernel<<<NN/64, 256>>>(x, mskp, nsc, nbi, Wl, bl, Wr, br,
                                   Wlg, blg, Wrg, brg, Wog, bog);
    einsum_mma_kernel<<<dim3(16, 128), 256, EIN_SMEM>>>();
    out_kernel<<<NN/64, 256>>>(gs, gb, Wout, bout, out);
}

// round 4
// speedup vs baseline: 1.3155x; 1.0570x over previous
#include <cuda_runtime.h>
#include <cuda_bf16.h>
#include <math.h>
#include <stdint.h>

// Problem constants
#define NTOK 512
#define DD   128
#define NN   (NTOK*NTOK)

// Scratch (static __device__ arrays — no allocation allowed)
// layouts:
//   g_lh/g_ll [c][i*512+k]  left  hi/lo bf16  (K-major for MMA A)
//   g_rh/g_rl [c][j*512+k]  right hi/lo bf16  (K-major for MMA B)
//   g_og      [c][j*512+i]  sigmoid(out-gate) f32
//   g_mix     [d][j*512+i]  einsum result f32 (transposed)
//   g_wsplit  [w][split][h][136] bf16 — pre-split/transposed weights
__device__ __nv_bfloat16 g_lh[33554432];
__device__ __nv_bfloat16 g_ll[33554432];
__device__ __nv_bfloat16 g_rh[33554432];
__device__ __nv_bfloat16 g_rl[33554432];
__device__ float         g_og [33554432];
__device__ float         g_mix[33554432];
__device__ __align__(16) __nv_bfloat16 g_wsplit[5 * 2 * 128 * 136];

// ---------------------------------------------------------------------------
// helpers
// ---------------------------------------------------------------------------
__device__ __forceinline__ uint32_t smem_u32(const void* p) {
    uint32_t a;
    asm("{ .reg .u64 t; cvta.to.shared.u64 t, %1; cvt.u32.u64 %0, t; }"
        : "=r"(a) : "l"(p));
    return a;
}

__device__ __forceinline__ void ldm4(uint32_t r[4], uint32_t addr) {
    asm volatile("ldmatrix.sync.aligned.m8n8.x4.shared.b16 {%0,%1,%2,%3}, [%4];"
                 : "=r"(r[0]), "=r"(r[1]), "=r"(r[2]), "=r"(r[3]) : "r"(addr));
}

__device__ __forceinline__ void mma_bf16(float acc[4], const uint32_t a[4],
                                         uint32_t b0, uint32_t b1) {
    asm volatile(
        "mma.sync.aligned.m16n8k16.row.col.f32.bf16.bf16.f32 "
        "{%0,%1,%2,%3}, {%4,%5,%6,%7}, {%8,%9}, {%0,%1,%2,%3};"
        : "+f"(acc[0]), "+f"(acc[1]), "+f"(acc[2]), "+f"(acc[3])
        : "r"(a[0]), "r"(a[1]), "r"(a[2]), "r"(a[3]), "r"(b0), "r"(b1));
}

__device__ __forceinline__ float sigmoidf_(float z) {
    return 1.f / (1.f + expf(-z));
}

__device__ __forceinline__ uint32_t split_pack(float v) {
    // low16 = hi bf16, high16 = lo bf16
    __nv_bfloat16 h = __float2bfloat16(v);
    __nv_bfloat16 l = __float2bfloat16(v - __bfloat162float(h));
    uint16_t hu = *(uint16_t*)&h, lu = *(uint16_t*)&l;
    return (uint32_t)hu | ((uint32_t)lu << 16);
}

// ---------------------------------------------------------------------------
// Kernel 0: split+transpose the 5 projection weights into B-operand layout.
// g_wsplit[w][s][h][136] bf16;  w order: 0=Wlg 1=Wl 2=Wrg 3=Wr 4=Wog
// ---------------------------------------------------------------------------
__global__ void wprep_kernel(const float* __restrict__ W0, const float* __restrict__ W1,
                             const float* __restrict__ W2, const float* __restrict__ W3,
                             const float* __restrict__ W4)
{
    const float* W = (blockIdx.x == 0) ? W0 : (blockIdx.x == 1) ? W1 :
                     (blockIdx.x == 2) ? W2 : (blockIdx.x == 3) ? W3 : W4;
    __nv_bfloat16* dst = g_wsplit + (size_t)blockIdx.x * 34816;
    for (int idx = threadIdx.x; idx < 16384; idx += 256) {
        const int d = idx >> 7, h = idx & 127;
        const float v = W[idx];
        __nv_bfloat16 hi = __float2bfloat16(v);
        __nv_bfloat16 lo = __float2bfloat16(v - __bfloat162float(hi));
        dst[h * 136 + d]         = hi;
        dst[17408 + h * 136 + d] = lo;
    }
}

// ---------------------------------------------------------------------------
// Kernel 1: LayerNorm + 5 projections via mma.sync (hi/lo split, 3 MMAs).
// Block = 128 rows (n1 contiguous, n2 fixed) x 128 channels, 8 warps (4m x 2n).
// Gate passes stage sigmoid in SMEM; value passes combine+split+store K-major.
// ---------------------------------------------------------------------------
#define K1_AH   0
#define K1_AL   34816
#define K1_WH   69632          // WH then WL contiguous (69632..139264)
#define K1_ST   139264         // stage: 128 x 129 f32 = 66048
#define K1_MS   205312         // mask_s: 128 f32
#define K1_SMEM 205824

template<int MODE>   // 0 = gate, 1 = value, 2 = out-gate
__device__ __forceinline__ void k1_pass(
    char* sm1, uint32_t sb, int w, const float* __restrict__ bias,
    int tid, int lane, int wm, int wn,
    __nv_bfloat16* dst_h, __nv_bfloat16* dst_l, float* dst_og, size_t gbase)
{
    __syncthreads();
    {   // copy pre-split weight (hi+lo, 69632B) into smem
        const uint4* src = (const uint4*)(g_wsplit + (size_t)w * 34816);
        uint4* d4 = (uint4*)(sm1 + K1_WH);
        #pragma unroll
        for (int it = 0; it < 17; ++it)
            d4[it * 256 + tid] = src[it * 256 + tid];
    }
    __syncthreads();

    const int g = lane >> 3, r = lane & 7;
    uint32_t aoff[2][2], boff[2][4];
    #pragma unroll
    for (int mi = 0; mi < 2; ++mi) {
        const uint32_t base = (uint32_t)((wm + mi*16 + r + (g&1)*8) * 272 + ((g>>1)*8)*2);
        aoff[0][mi] = sb + K1_AH + base;
        aoff[1][mi] = sb + K1_AL + base;
    }
    #pragma unroll
    for (int p = 0; p < 4; ++p) {
        const uint32_t base = (uint32_t)((wn + p*16 + r + (g>>1)*8) * 272 + ((g&1)*8)*2);
        boff[0][p] = sb + K1_WH + base;
        boff[1][p] = sb + K1_WH + 34816 + base;
    }

    float acc[2][8][4] = {};
    #pragma unroll
    for (int kc = 0; kc < 8; ++kc) {
        const uint32_t off = (uint32_t)kc * 32;
        uint32_t AH[2][4], AL[2][4], BH[4][4], BL[4][4];
        #pragma unroll
        for (int mi = 0; mi < 2; ++mi) {
            ldm4(AH[mi], aoff[0][mi] + off);
            ldm4(AL[mi], aoff[1][mi] + off);
        }
        #pragma unroll
        for (int p = 0; p < 4; ++p) {
            ldm4(BH[p], boff[0][p] + off);
            ldm4(BL[p], boff[1][p] + off);
        }
        #pragma unroll
        for (int mi = 0; mi < 2; ++mi)
            #pragma unroll
            for (int ni = 0; ni < 8; ++ni) {
                const int p = ni >> 1, h = (ni & 1) * 2;
                mma_bf16(acc[mi][ni], AH[mi], BH[p][h], BH[p][h+1]);
                mma_bf16(acc[mi][ni], AH[mi], BL[p][h], BL[p][h+1]);
                mma_bf16(acc[mi][ni], AL[mi], BH[p][h], BH[p][h+1]);
            }
    }

    float*    stagef = (float*)(sm1 + K1_ST);
    uint32_t* stageu = (uint32_t*)(sm1 + K1_ST);
    const float* mask_s = (const float*)(sm1 + K1_MS);

    #pragma unroll
    for (int mi = 0; mi < 2; ++mi)
        #pragma unroll
        for (int ni = 0; ni < 8; ++ni) {
            const int m0 = wm + mi*16 + (lane >> 2);
            const int n  = wn + ni*8 + (lane & 3)*2;
            const float b0 = bias[n], b1 = bias[n+1];
            float* a = acc[mi][ni];
            if (MODE == 0) {
                stagef[ m0   *129 + n    ] = sigmoidf_(a[0] + b0);
                stagef[ m0   *129 + n + 1] = sigmoidf_(a[1] + b1);
                stagef[(m0+8)*129 + n    ] = sigmoidf_(a[2] + b0);
                stagef[(m0+8)*129 + n + 1] = sigmoidf_(a[3] + b1);
            } else if (MODE == 1) {
                const float mk0 = mask_s[m0], mk1 = mask_s[m0 + 8];
                float o0 = (a[0] + b0) * mk0 * stagef[ m0   *129 + n    ];
                float o1 = (a[1] + b1) * mk0 * stagef[ m0   *129 + n + 1];
                float o2 = (a[2] + b0) * mk1 * stagef[(m0+8)*129 + n    ];
                float o3 = (a[3] + b1) * mk1 * stagef[(m0+8)*129 + n + 1];
                stageu[ m0   *129 + n    ] = split_pack(o0);
                stageu[ m0   *129 + n + 1] = split_pack(o1);
                stageu[(m0+8)*129 + n    ] = split_pack(o2);
                stageu[(m0+8)*129 + n + 1] = split_pack(o3);
            } else {
                stagef[ m0   *129 + n    ] = sigmoidf_(a[0] + b0);
                stagef[ m0   *129 + n + 1] = sigmoidf_(a[1] + b1);
                stagef[(m0+8)*129 + n    ] = sigmoidf_(a[2] + b0);
                stagef[(m0+8)*129 + n + 1] = sigmoidf_(a[3] + b1);
            }
        }

    if (MODE == 1) {
        __syncthreads();
        #pragma unroll
        for (int it = 0; it < 32; ++it) {
            const int idx = it * 256 + tid;        // 8192 = 128c x 64 row-pairs
            const int c  = idx >> 6;
            const int rp = (idx & 63) * 2;
            const uint32_t u0 = stageu[ rp      * 129 + c];
            const uint32_t u1 = stageu[(rp + 1) * 129 + c];
            const size_t addr = (size_t)c * NN + gbase + rp;
            *(uint32_t*)(dst_h + addr) = (u0 & 0xffffu) | (u1 << 16);
            *(uint32_t*)(dst_l + addr) = (u0 >> 16) | (u1 & 0xffff0000u);
        }
    } else if (MODE == 2) {
        __syncthreads();
        #pragma unroll
        for (int it = 0; it < 64; ++it) {
            const int idx = it * 256 + tid;        // 16384 floats
            const int c = idx >> 7, rr = idx & 127;
            dst_og[(size_t)c * NN + gbase + rr] = stagef[rr * 129 + c];
        }
    }
}

__global__ __launch_bounds__(256, 1) void ln_proj_mma_kernel(
    const float* __restrict__ x,   const float* __restrict__ msk,
    const float* __restrict__ nsc, const float* __restrict__ nbi,
    const float* __restrict__ bl,  const float* __restrict__ br,
    const float* __restrict__ blg, const float* __restrict__ brg,
    const float* __restrict__ bog)
{
    extern __shared__ __align__(16) char sm1[];
    const int tid  = threadIdx.x;
    const int lane = tid & 31;
    const int wid  = tid >> 5;
    const int n2   = blockIdx.x & 511;
    const int n1b  = (blockIdx.x >> 9) << 7;
    const uint32_t sb = smem_u32(sm1);

    // ---- LayerNorm: 2 threads per row, 64 elems each; write bf16 hi/lo A ----
    {
        const int row = tid >> 1, sub = tid & 1;
        const float4* xr = reinterpret_cast<const float4*>(
                               x + ((size_t)(n1b + row) * 512 + n2) * DD) + sub * 16;
        float4 v[16];
        float s = 0.f, ss = 0.f;
        #pragma unroll
        for (int q = 0; q < 16; ++q) {
            v[q] = xr[q];
            s  += v[q].x + v[q].y + v[q].z + v[q].w;
            ss += v[q].x*v[q].x + v[q].y*v[q].y + v[q].z*v[q].z + v[q].w*v[q].w;
        }
        s  += __shfl_xor_sync(0xffffffffu, s, 1);
        ss += __shfl_xor_sync(0xffffffffu, ss, 1);
        const float mu   = s * (1.f/128.f);
        const float var  = ss * (1.f/128.f) - mu*mu;
        const float rstd = rsqrtf(var + 1e-6f);
        #pragma unroll
        for (int q = 0; q < 16; ++q) {
            const int d0 = sub*64 + q*4;
            float a0 = (v[q].x - mu)*rstd*__ldg(&nsc[d0+0]) + __ldg(&nbi[d0+0]);
            float a1 = (v[q].y - mu)*rstd*__ldg(&nsc[d0+1]) + __ldg(&nbi[d0+1]);
            float a2 = (v[q].z - mu)*rstd*__ldg(&nsc[d0+2]) + __ldg(&nbi[d0+2]);
            float a3 = (v[q].w - mu)*rstd*__ldg(&nsc[d0+3]) + __ldg(&nbi[d0+3]);
            uint32_t p0 = split_pack(a0), p1 = split_pack(a1);
            uint32_t p2 = split_pack(a2), p3 = split_pack(a3);
            // hi pairs / lo pairs
            uint2 hw, lw;
            hw.x = (p0 & 0xffffu) | (p1 << 16);
            hw.y = (p2 & 0xffffu) | (p3 << 16);
            lw.x = (p0 >> 16) | (p1 & 0xffff0000u);
            lw.y = (p2 >> 16) | (p3 & 0xffff0000u);
            *(uint2*)(sm1 + K1_AH + row*272 + d0*2) = hw;
            *(uint2*)(sm1 + K1_AL + row*272 + d0*2) = lw;
        }
        if (sub == 0)
            ((float*)(sm1 + K1_MS))[row] = msk[n1b + row] * msk[n2];
    }

    const int wm = (wid & 3) * 32;
    const int wn = (wid >> 2) * 64;
    const size_t gbase = (size_t)n2 * 512 + n1b;

    k1_pass<0>(sm1, sb, 0, blg, tid, lane, wm, wn, 0, 0, 0, gbase);
    k1_pass<1>(sm1, sb, 1, bl,  tid, lane, wm, wn, g_lh, g_ll, 0, gbase);
    k1_pass<0>(sm1, sb, 2, brg, tid, lane, wm, wn, 0, 0, 0, gbase);
    k1_pass<1>(sm1, sb, 3, br,  tid, lane, wm, wn, g_rh, g_rl, 0, gbase);
    k1_pass<2>(sm1, sb, 4, bog, tid, lane, wm, wn, 0, 0, g_og, gbase);
}

// ---------------------------------------------------------------------------
// Kernel 2: einsum 'bkid,bkjd->bijd' via mma.sync bf16 (hi/lo split, 3 MMAs).
// ---------------------------------------------------------------------------
#define EIN_STAGE  40960
#define EIN_SMEM   (2*EIN_STAGE)

__global__ __launch_bounds__(256) void einsum_mma_kernel()
{
    extern __shared__ __align__(16) char esm[];
    const int tid  = threadIdx.x;
    const int lane = tid & 31;
    const int wid  = tid >> 5;
    const int d    = blockIdx.y;
    const int i0   = (blockIdx.x & 3) * 128;
    const int j0   = (blockIdx.x >> 2) * 128;
    const uint32_t sbm = smem_u32(esm);

    const __nv_bfloat16* __restrict__ pAH = g_lh + (size_t)d*NN;
    const __nv_bfloat16* __restrict__ pAL = g_ll + (size_t)d*NN;
    const __nv_bfloat16* __restrict__ pBH = g_rh + (size_t)d*NN;
    const __nv_bfloat16* __restrict__ pBL = g_rl + (size_t)d*NN;

    const __nv_bfloat16* gptr[8];
    uint32_t soff[8];
    #pragma unroll
    for (int it = 0; it < 8; ++it) {
        const int idx = it*256 + tid;
        const int arr = idx >> 9;
        const int rem = idx & 511;
        const int row = rem >> 2;
        const int seg = rem & 3;
        const __nv_bfloat16* src =
            (arr == 0) ? pAH : (arr == 1) ? pAL : (arr == 2) ? pBH : pBL;
        const int r0 = (arr < 2) ? i0 : j0;
        gptr[it] = src + (size_t)(r0 + row)*512 + seg*8;
        soff[it] = (uint32_t)(arr*10240 + row*80 + seg*16);
    }

    const int g = lane >> 3, r = lane & 7;
    const int wm = (wid & 3) * 32;
    const int wn = (wid >> 2) * 64;
    uint32_t aoff[2][2];
    #pragma unroll
    for (int mi = 0; mi < 2; ++mi) {
        const uint32_t base = (uint32_t)((wm + mi*16 + r + (g&1)*8)*80 + ((g>>1)*8)*2);
        aoff[0][mi] = sbm + base;
        aoff[1][mi] = sbm + 10240 + base;
    }
    uint32_t boff[2][4];
    #pragma unroll
    for (int p = 0; p < 4; ++p) {
        const uint32_t base = (uint32_t)((wn + p*16 + r + (g>>1)*8)*80 + ((g&1)*8)*2);
        boff[0][p] = sbm + 20480 + base;
        boff[1][p] = sbm + 30720 + base;
    }

    float acc[2][8][4] = {};
    uint4 v[8];

    #pragma unroll
    for (int it = 0; it < 8; ++it) v[it] = *(const uint4*)(gptr[it]);
    #pragma unroll
    for (int it = 0; it < 8; ++it) *(uint4*)(esm + soff[it]) = v[it];
    __syncthreads();

    #pragma unroll 1
    for (int kc = 0; kc < 16; ++kc) {
        const uint32_t stg = (uint32_t)(kc & 1) * EIN_STAGE;
        if (kc < 15) {
            const int kb = (kc + 1) * 32;
            #pragma unroll
            for (int it = 0; it < 8; ++it)
                v[it] = *(const uint4*)(gptr[it] + kb);
        }
        #pragma unroll
        for (int ks2 = 0; ks2 < 2; ++ks2) {
            const uint32_t off = stg + (uint32_t)ks2 * 32;
            uint32_t AH[2][4], AL[2][4], BH[4][4], BL[4][4];
            #pragma unroll
            for (int mi = 0; mi < 2; ++mi) {
                ldm4(AH[mi], aoff[0][mi] + off);
                ldm4(AL[mi], aoff[1][mi] + off);
            }
            #pragma unroll
            for (int p = 0; p < 4; ++p) {
                ldm4(BH[p], boff[0][p] + off);
                ldm4(BL[p], boff[1][p] + off);
            }
            #pragma unroll
            for (int mi = 0; mi < 2; ++mi)
                #pragma unroll
                for (int ni = 0; ni < 8; ++ni) {
                    const int p = ni >> 1, h = (ni & 1) * 2;
                    mma_bf16(acc[mi][ni], AH[mi], BH[p][h], BH[p][h+1]);
                    mma_bf16(acc[mi][ni], AH[mi], BL[p][h], BL[p][h+1]);
                    mma_bf16(acc[mi][ni], AL[mi], BH[p][h], BH[p][h+1]);
                }
        }
        if (kc < 15) {
            const uint32_t nstg = (uint32_t)((kc + 1) & 1) * EIN_STAGE;
            #pragma unroll
            for (int it = 0; it < 8; ++it)
                *(uint4*)(esm + nstg + soff[it]) = v[it];
            __syncthreads();
        }
    }

    __syncthreads();
    float* smT = (float*)esm;
    #pragma unroll
    for (int mi = 0; mi < 2; ++mi)
        #pragma unroll
        for (int ni = 0; ni < 8; ++ni) {
            const int m = wm + mi*16 + (lane >> 2);
            const int j = wn + ni*8 + (lane & 3)*2;
            smT[(j  )*129 + m    ] = acc[mi][ni][0];
            smT[(j+1)*129 + m    ] = acc[mi][ni][1];
            smT[(j  )*129 + m + 8] = acc[mi][ni][2];
            smT[(j+1)*129 + m + 8] = acc[mi][ni][3];
        }
    __syncthreads();

    float* gm = g_mix + (size_t)d * NN;
    #pragma unroll
    for (int it = 0; it < 16; ++it) {
        const int idx = it*256 + tid;
        const int j = idx >> 5, c4 = idx & 31;
        float4 o;
        o.x = smT[j*129 + c4*4 + 0];
        o.y = smT[j*129 + c4*4 + 1];
        o.z = smT[j*129 + c4*4 + 2];
        o.w = smT[j*129 + c4*4 + 3];
        *reinterpret_cast<float4*>(gm + (size_t)(j0 + j)*512 + i0 + c4*4) = o;
    }
}

// ---------------------------------------------------------------------------
// Kernel 3: out-LayerNorm (over d) * out_gate, then @ W_out + b_out.
// ---------------------------------------------------------------------------
__global__ __launch_bounds__(256) void out_kernel(
    const float* __restrict__ gs, const float* __restrict__ gb,
    const float* __restrict__ Wout, const float* __restrict__ bout,
    float* __restrict__ out)
{
    __shared__ float gg_s[128][64];
    __shared__ float w_s[16][128];
    __shared__ float red[2][4][64];

    const int tid = threadIdx.x;
    const int rt0 = blockIdx.x * 64;
    const int j   = rt0 >> 9;
    const int ibase = rt0 & 511;
    const int rl  = tid & 63;
    const int dg  = tid >> 6;

    float s = 0.f, q = 0.f;
    #pragma unroll 4
    for (int dd = dg*32; dd < dg*32 + 32; ++dd) {
        float v = g_mix[(size_t)dd*NN + rt0 + rl];
        s += v; q += v*v;
    }
    red[0][dg][rl] = s; red[1][dg][rl] = q;
    __syncthreads();
    const float S = red[0][0][rl] + red[0][1][rl] + red[0][2][rl] + red[0][3][rl];
    const float Q = red[1][0][rl] + red[1][1][rl] + red[1][2][rl] + red[1][3][rl];
    const float mu   = S * (1.f/128.f);
    const float rstd = rsqrtf(Q * (1.f/128.f) - mu*mu + 1e-6f);

    #pragma unroll 4
    for (int dd = dg*32; dd < dg*32 + 32; ++dd) {
        float v = g_mix[(size_t)dd*NN + rt0 + rl];
        float o = g_og [(size_t)dd*NN + rt0 + rl];
        gg_s[dd][rl] = ((v - mu)*rstd*gs[dd] + gb[dd]) * o;
    }
    __syncthreads();

    const int tx = tid & 15, ty = tid >> 4;
    float acc[4][8] = {};
    #pragma unroll 1
    for (int dc = 0; dc < 128; dc += 16) {
        const int dl = tid >> 4, cg = (tid & 15) * 8;
        *(float4*)&w_s[dl][cg]     = *(const float4*)&Wout[(dc + dl)*DD + cg];
        *(float4*)&w_s[dl][cg + 4] = *(const float4*)&Wout[(dc + dl)*DD + cg + 4];
        __syncthreads();
        #pragma unroll
        for (int u = 0; u < 16; ++u) {
            float4 a  = *(const float4*)&gg_s[dc + u][4*ty];
            float4 b0 = *(const float4*)&w_s[u][8*tx];
            float4 b1 = *(const float4*)&w_s[u][8*tx + 4];
            float av[4] = {a.x, a.y, a.z, a.w};
            float bv[8] = {b0.x, b0.y, b0.z, b0.w, b1.x, b1.y, b1.z, b1.w};
            #pragma unroll
            for (int ii = 0; ii < 4; ++ii)
                #pragma unroll
                for (int cc = 0; cc < 8; ++cc)
                    acc[ii][cc] += av[ii] * bv[cc];
        }
        __syncthreads();
    }

    float* sbuf = &gg_s[0][0];
    const float4 bo0 = *(const float4*)&bout[8*tx];
    const float4 bo1 = *(const float4*)&bout[8*tx + 4];
    #pragma unroll
    for (int ii = 0; ii < 4; ++ii) {
        float* rowp = sbuf + (4*ty + ii)*128 + 8*tx;
        rowp[0] = acc[ii][0] + bo0.x;
        rowp[1] = acc[ii][1] + bo0.y;
        rowp[2] = acc[ii][2] + bo0.z;
        rowp[3] = acc[ii][3] + bo0.w;
        rowp[4] = acc[ii][4] + bo1.x;
        rowp[5] = acc[ii][5] + bo1.y;
        rowp[6] = acc[ii][6] + bo1.z;
        rowp[7] = acc[ii][7] + bo1.w;
    }
    __syncthreads();
    #pragma unroll
    for (int it = 0; it < 8; ++it) {
        const int idx = it * 256 + tid;
        const int row = idx >> 5, c4 = idx & 31;
        float4 v = *reinterpret_cast<float4*>(&sbuf[row*128 + c4*4]);
        *reinterpret_cast<float4*>(
            out + ((size_t)(ibase + row)*512 + j)*DD + c4*4) = v;
    }
}

// ---------------------------------------------------------------------------
extern "C" void kernel_launch(void* const* d_in, const int* in_sizes, int n_in,
                              void* d_out, int out_size)
{
    const float* x    = (const float*)d_in[0];
    const float* mskp = (const float*)d_in[1];
    const float* nsc  = (const float*)d_in[2];
    const float* nbi  = (const float*)d_in[3];
    const float* Wl   = (const float*)d_in[4];
    const float* bl   = (const float*)d_in[5];
    const float* Wr   = (const float*)d_in[6];
    const float* br   = (const float*)d_in[7];
    const float* Wlg  = (const float*)d_in[8];
    const float* blg  = (const float*)d_in[9];
    const float* Wrg  = (const float*)d_in[10];
    const float* brg  = (const float*)d_in[11];
    const float* Wog  = (const float*)d_in[12];
    const float* bog  = (const float*)d_in[13];
    const float* gs   = (const float*)d_in[14];
    const float* gb   = (const float*)d_in[15];
    const float* Wout = (const float*)d_in[16];
    const float* bout = (const float*)d_in[17];
    float* out = (float*)d_out;

    cudaFuncSetAttribute(einsum_mma_kernel,
                         cudaFuncAttributeMaxDynamicSharedMemorySize, EIN_SMEM);
    cudaFuncSetAttribute(ln_proj_mma_kernel,
                         cudaFuncAttributeMaxDynamicSharedMemorySize, K1_SMEM);

    wprep_kernel<<<5, 256>>>(Wlg, Wl, Wrg, Wr, Wog);
    ln_proj_mma_kernel<<<2048, 256, K1_SMEM>>>(x, mskp, nsc, nbi,
                                               bl, br, blg, brg, bog);
    einsum_mma_kernel<<<dim3(16, 128), 256, EIN_SMEM>>>();
    out_kernel<<<NN/64, 256>>>(gs, gb, Wout, bout, out);
}

// round 5
// speedup vs baseline: 1.4105x; 1.0722x over previous
#include <cuda_runtime.h>
#include <cuda_bf16.h>
#include <math.h>
#include <stdint.h>

// Problem constants
#define NTOK 512
#define DD   128
#define NN   (NTOK*NTOK)

// Scratch (static __device__ arrays — no allocation allowed)
//   g_lh/g_ll [c][i*512+k]  left  hi/lo bf16  (K-major for MMA A)
//   g_rh/g_rl [c][j*512+k]  right hi/lo bf16  (K-major for MMA B)
//   g_og      [c][j*512+i]  sigmoid(out-gate) f32
//   g_mix     [d][j*512+i]  einsum result f32 (transposed)
//   g_wfrag   [w][kc][p][spl][lane] uint4 — B-fragment-ready weights
//             w: 0=Wlg 1=Wl 2=Wrg 3=Wr 4=Wog 5=Wout
__device__ __nv_bfloat16 g_lh[33554432];
__device__ __nv_bfloat16 g_ll[33554432];
__device__ __nv_bfloat16 g_rh[33554432];
__device__ __nv_bfloat16 g_rl[33554432];
__device__ float         g_og [33554432];
__device__ float         g_mix[33554432];
__device__ __align__(16) uint4 g_wfrag[6 * 4096];

// ---------------------------------------------------------------------------
// helpers
// ---------------------------------------------------------------------------
__device__ __forceinline__ uint32_t smem_u32(const void* p) {
    uint32_t a;
    asm("{ .reg .u64 t; cvta.to.shared.u64 t, %1; cvt.u32.u64 %0, t; }"
        : "=r"(a) : "l"(p));
    return a;
}

__device__ __forceinline__ void ldm4(uint32_t r[4], uint32_t addr) {
    asm volatile("ldmatrix.sync.aligned.m8n8.x4.shared.b16 {%0,%1,%2,%3}, [%4];"
                 : "=r"(r[0]), "=r"(r[1]), "=r"(r[2]), "=r"(r[3]) : "r"(addr));
}

__device__ __forceinline__ void mma_bf16(float acc[4], const uint32_t a[4],
                                         uint32_t b0, uint32_t b1) {
    asm volatile(
        "mma.sync.aligned.m16n8k16.row.col.f32.bf16.bf16.f32 "
        "{%0,%1,%2,%3}, {%4,%5,%6,%7}, {%8,%9}, {%0,%1,%2,%3};"
        : "+f"(acc[0]), "+f"(acc[1]), "+f"(acc[2]), "+f"(acc[3])
        : "r"(a[0]), "r"(a[1]), "r"(a[2]), "r"(a[3]), "r"(b0), "r"(b1));
}

__device__ __forceinline__ float sigmoidf_(float z) {
    return 1.f / (1.f + expf(-z));
}

__device__ __forceinline__ uint32_t split_pack(float v) {
    // low16 = hi bf16, high16 = lo bf16
    __nv_bfloat16 h = __float2bfloat16(v);
    __nv_bfloat16 l = __float2bfloat16(v - __bfloat162float(h));
    uint16_t hu = *(uint16_t*)&h, lu = *(uint16_t*)&l;
    return (uint32_t)hu | ((uint32_t)lu << 16);
}

// ---------------------------------------------------------------------------
// Kernel 0: weights -> B-fragment layout (hi/lo), register-ready for mma.sync.
// For m16n8k16 row.col: lane l of an n8k16 tile holds
//   b0 = {B[k0][n], B[k0+1][n]}, b1 = {B[k0+8][n], B[k0+9][n]},
//   n = tile_n + (l>>2), k0 = tile_k + 2*(l&3).  uint4 = two n8 tiles.
// ---------------------------------------------------------------------------
__global__ void wprep_kernel(const float* __restrict__ W0, const float* __restrict__ W1,
                             const float* __restrict__ W2, const float* __restrict__ W3,
                             const float* __restrict__ W4, const float* __restrict__ W5)
{
    const float* W = (blockIdx.x == 0) ? W0 : (blockIdx.x == 1) ? W1 :
                     (blockIdx.x == 2) ? W2 : (blockIdx.x == 3) ? W3 :
                     (blockIdx.x == 4) ? W4 : W5;
    uint4* dst = g_wfrag + blockIdx.x * 4096;
    for (int idx = threadIdx.x; idx < 4096; idx += 256) {
        const int lane = idx & 31;
        const int spl  = (idx >> 5) & 1;
        const int p    = (idx >> 6) & 7;
        const int kc   = idx >> 9;
        const int nf = p * 16 + (lane >> 2);
        const int k0 = kc * 16 + 2 * (lane & 3);
        uint16_t e[8];
        #pragma unroll
        for (int q = 0; q < 8; ++q) {
            const int k = k0 + (q & 1) + ((q >> 1) & 1) * 8;
            const int n = nf + (q >> 2) * 8;
            const float v = W[k * 128 + n];
            __nv_bfloat16 h = __float2bfloat16(v);
            __nv_bfloat16 l = __float2bfloat16(v - __bfloat162float(h));
            e[q] = spl ? *(uint16_t*)&l : *(uint16_t*)&h;
        }
        uint4 o;
        o.x = (uint32_t)e[0] | ((uint32_t)e[1] << 16);
        o.y = (uint32_t)e[2] | ((uint32_t)e[3] << 16);
        o.z = (uint32_t)e[4] | ((uint32_t)e[5] << 16);
        o.w = (uint32_t)e[6] | ((uint32_t)e[7] << 16);
        dst[idx] = o;
    }
}

// ---------------------------------------------------------------------------
// Kernel 1: LayerNorm + 5 projections. Value+gate fused in one kc loop
// (two acc sets, sigmoid in-register). Weights via LDG fragments (no smem).
// Block = 128 rows (n1 contiguous, n2 fixed) x 128 ch, 8 warps (4m x 2n).
// ---------------------------------------------------------------------------
#define K1_AH   0
#define K1_AL   34816
#define K1_ST   69632          // stage: 128 x 129 f32 = 66048
#define K1_MS   135680         // mask_s: 128 f32
#define K1_SMEM 136192

template<bool PAIR>   // true: value+gate pair; false: out-gate only
__device__ __forceinline__ void k1_pass2(
    char* sm1, uint32_t sb, int wv, int wg,
    const float* __restrict__ bv, const float* __restrict__ bg,
    int tid, int lane, int wm, int wn,
    __nv_bfloat16* dst_h, __nv_bfloat16* dst_l, float* dst_og, size_t gbase)
{
    const int g = lane >> 3, r = lane & 7;
    uint32_t aoffH[2], aoffL[2];
    #pragma unroll
    for (int mi = 0; mi < 2; ++mi) {
        const uint32_t base = (uint32_t)((wm + mi*16 + r + (g&1)*8) * 272 + ((g>>1)*8)*2);
        aoffH[mi] = sb + K1_AH + base;
        aoffL[mi] = sb + K1_AL + base;
    }
    const uint4* __restrict__ fv = g_wfrag + wv * 4096 + lane;
    const uint4* __restrict__ fg = g_wfrag + wg * 4096 + lane;
    const int pbase = wn >> 4;

    float accV[2][8][4] = {};
    float accG[PAIR ? 2 : 1][8][4] = {};

    #pragma unroll
    for (int kc = 0; kc < 8; ++kc) {
        uint32_t AH[2][4], AL[2][4];
        #pragma unroll
        for (int mi = 0; mi < 2; ++mi) {
            ldm4(AH[mi], aoffH[mi] + kc*32);
            ldm4(AL[mi], aoffL[mi] + kc*32);
        }
        #pragma unroll
        for (int p4 = 0; p4 < 4; ++p4) {
            const int fidx = ((kc*8 + pbase + p4) * 2) * 32;
            const uint4 bvh = fv[fidx];
            const uint4 bvl = fv[fidx + 32];
            uint4 bgh, bgl;
            if (PAIR) { bgh = fg[fidx]; bgl = fg[fidx + 32]; }
            #pragma unroll
            for (int ns = 0; ns < 2; ++ns) {
                const int ni = p4*2 + ns;
                const uint32_t v0 = ns ? bvh.z : bvh.x, v1 = ns ? bvh.w : bvh.y;
                const uint32_t l0 = ns ? bvl.z : bvl.x, l1 = ns ? bvl.w : bvl.y;
                #pragma unroll
                for (int mi = 0; mi < 2; ++mi) {
                    mma_bf16(accV[mi][ni], AH[mi], v0, v1);
                    mma_bf16(accV[mi][ni], AH[mi], l0, l1);
                    mma_bf16(accV[mi][ni], AL[mi], v0, v1);
                }
                if (PAIR) {
                    const uint32_t g0 = ns ? bgh.z : bgh.x, g1 = ns ? bgh.w : bgh.y;
                    const uint32_t m0 = ns ? bgl.z : bgl.x, m1 = ns ? bgl.w : bgl.y;
                    #pragma unroll
                    for (int mi = 0; mi < 2; ++mi) {
                        mma_bf16(accG[mi][ni], AH[mi], g0, g1);
                        mma_bf16(accG[mi][ni], AH[mi], m0, m1);
                        mma_bf16(accG[mi][ni], AL[mi], g0, g1);
                    }
                }
            }
        }
    }

    float*    stagef = (float*)(sm1 + K1_ST);
    uint32_t* stageu = (uint32_t*)(sm1 + K1_ST);
    const float* mask_s = (const float*)(sm1 + K1_MS);

    #pragma unroll
    for (int mi = 0; mi < 2; ++mi)
        #pragma unroll
        for (int ni = 0; ni < 8; ++ni) {
            const int m0 = wm + mi*16 + (lane >> 2);
            const int n  = wn + ni*8 + (lane & 3)*2;
            const float b0 = __ldg(bv + n), b1 = __ldg(bv + n + 1);
            float* a = accV[mi][ni];
            if (PAIR) {
                const float c0 = __ldg(bg + n), c1 = __ldg(bg + n + 1);
                const float* gacc = accG[mi][ni];
                const float mk0 = mask_s[m0], mk1 = mask_s[m0 + 8];
                stageu[ m0   *129 + n    ] = split_pack((a[0]+b0)*mk0*sigmoidf_(gacc[0]+c0));
                stageu[ m0   *129 + n + 1] = split_pack((a[1]+b1)*mk0*sigmoidf_(gacc[1]+c1));
                stageu[(m0+8)*129 + n    ] = split_pack((a[2]+b0)*mk1*sigmoidf_(gacc[2]+c0));
                stageu[(m0+8)*129 + n + 1] = split_pack((a[3]+b1)*mk1*sigmoidf_(gacc[3]+c1));
            } else {
                stagef[ m0   *129 + n    ] = sigmoidf_(a[0] + b0);
                stagef[ m0   *129 + n + 1] = sigmoidf_(a[1] + b1);
                stagef[(m0+8)*129 + n    ] = sigmoidf_(a[2] + b0);
                stagef[(m0+8)*129 + n + 1] = sigmoidf_(a[3] + b1);
            }
        }
    __syncthreads();

    if (PAIR) {
        #pragma unroll
        for (int it = 0; it < 32; ++it) {
            const int idx = it * 256 + tid;        // 8192 = 128c x 64 row-pairs
            const int c  = idx >> 6;
            const int rp = (idx & 63) * 2;
            const uint32_t u0 = stageu[ rp      * 129 + c];
            const uint32_t u1 = stageu[(rp + 1) * 129 + c];
            const size_t addr = (size_t)c * NN + gbase + rp;
            *(uint32_t*)(dst_h + addr) = (u0 & 0xffffu) | (u1 << 16);
            *(uint32_t*)(dst_l + addr) = (u0 >> 16) | (u1 & 0xffff0000u);
        }
    } else {
        #pragma unroll
        for (int it = 0; it < 64; ++it) {
            const int idx = it * 256 + tid;        // 16384 floats
            const int c = idx >> 7, rr = idx & 127;
            dst_og[(size_t)c * NN + gbase + rr] = stagef[rr * 129 + c];
        }
    }
    __syncthreads();
}

__global__ __launch_bounds__(256, 1) void ln_proj_mma_kernel(
    const float* __restrict__ x,   const float* __restrict__ msk,
    const float* __restrict__ nsc, const float* __restrict__ nbi,
    const float* __restrict__ bl,  const float* __restrict__ br,
    const float* __restrict__ blg, const float* __restrict__ brg,
    const float* __restrict__ bog)
{
    extern __shared__ __align__(16) char sm1[];
    const int tid  = threadIdx.x;
    const int lane = tid & 31;
    const int wid  = tid >> 5;
    const int n2   = blockIdx.x & 511;
    const int n1b  = (blockIdx.x >> 9) << 7;
    const uint32_t sb = smem_u32(sm1);

    // ---- LayerNorm: 2 threads per row, 64 elems each; write bf16 hi/lo A ----
    {
        const int row = tid >> 1, sub = tid & 1;
        const float4* xr = reinterpret_cast<const float4*>(
                               x + ((size_t)(n1b + row) * 512 + n2) * DD) + sub * 16;
        float4 v[16];
        float s = 0.f, ss = 0.f;
        #pragma unroll
        for (int q = 0; q < 16; ++q) {
            v[q] = xr[q];
            s  += v[q].x + v[q].y + v[q].z + v[q].w;
            ss += v[q].x*v[q].x + v[q].y*v[q].y + v[q].z*v[q].z + v[q].w*v[q].w;
        }
        s  += __shfl_xor_sync(0xffffffffu, s, 1);
        ss += __shfl_xor_sync(0xffffffffu, ss, 1);
        const float mu   = s * (1.f/128.f);
        const float var  = ss * (1.f/128.f) - mu*mu;
        const float rstd = rsqrtf(var + 1e-6f);
        #pragma unroll
        for (int q = 0; q < 16; ++q) {
            const int d0 = sub*64 + q*4;
            float a0 = (v[q].x - mu)*rstd*__ldg(&nsc[d0+0]) + __ldg(&nbi[d0+0]);
            float a1 = (v[q].y - mu)*rstd*__ldg(&nsc[d0+1]) + __ldg(&nbi[d0+1]);
            float a2 = (v[q].z - mu)*rstd*__ldg(&nsc[d0+2]) + __ldg(&nbi[d0+2]);
            float a3 = (v[q].w - mu)*rstd*__ldg(&nsc[d0+3]) + __ldg(&nbi[d0+3]);
            uint32_t p0 = split_pack(a0), p1 = split_pack(a1);
            uint32_t p2 = split_pack(a2), p3 = split_pack(a3);
            uint2 hw, lw;
            hw.x = (p0 & 0xffffu) | (p1 << 16);
            hw.y = (p2 & 0xffffu) | (p3 << 16);
            lw.x = (p0 >> 16) | (p1 & 0xffff0000u);
            lw.y = (p2 >> 16) | (p3 & 0xffff0000u);
            *(uint2*)(sm1 + K1_AH + row*272 + d0*2) = hw;
            *(uint2*)(sm1 + K1_AL + row*272 + d0*2) = lw;
        }
        if (sub == 0)
            ((float*)(sm1 + K1_MS))[row] = msk[n1b + row] * msk[n2];
    }
    __syncthreads();

    const int wm = (wid & 3) * 32;
    const int wn = (wid >> 2) * 64;
    const size_t gbase = (size_t)n2 * 512 + n1b;

    k1_pass2<true >(sm1, sb, 1, 0, bl,  blg, tid, lane, wm, wn, g_lh, g_ll, 0, gbase);
    k1_pass2<true >(sm1, sb, 3, 2, br,  brg, tid, lane, wm, wn, g_rh, g_rl, 0, gbase);
    k1_pass2<false>(sm1, sb, 4, 4, bog, bog, tid, lane, wm, wn, 0, 0, g_og, gbase);
}

// ---------------------------------------------------------------------------
// Kernel 2: einsum 'bkid,bkjd->bijd' via mma.sync bf16 (hi/lo split, 3 MMAs).
// (unchanged from round 4 — known good)
// ---------------------------------------------------------------------------
#define EIN_STAGE  40960
#define EIN_SMEM   (2*EIN_STAGE)

__global__ __launch_bounds__(256) void einsum_mma_kernel()
{
    extern __shared__ __align__(16) char esm[];
    const int tid  = threadIdx.x;
    const int lane = tid & 31;
    const int wid  = tid >> 5;
    const int d    = blockIdx.y;
    const int i0   = (blockIdx.x & 3) * 128;
    const int j0   = (blockIdx.x >> 2) * 128;
    const uint32_t sbm = smem_u32(esm);

    const __nv_bfloat16* __restrict__ pAH = g_lh + (size_t)d*NN;
    const __nv_bfloat16* __restrict__ pAL = g_ll + (size_t)d*NN;
    const __nv_bfloat16* __restrict__ pBH = g_rh + (size_t)d*NN;
    const __nv_bfloat16* __restrict__ pBL = g_rl + (size_t)d*NN;

    const __nv_bfloat16* gptr[8];
    uint32_t soff[8];
    #pragma unroll
    for (int it = 0; it < 8; ++it) {
        const int idx = it*256 + tid;
        const int arr = idx >> 9;
        const int rem = idx & 511;
        const int row = rem >> 2;
        const int seg = rem & 3;
        const __nv_bfloat16* src =
            (arr == 0) ? pAH : (arr == 1) ? pAL : (arr == 2) ? pBH : pBL;
        const int r0 = (arr < 2) ? i0 : j0;
        gptr[it] = src + (size_t)(r0 + row)*512 + seg*8;
        soff[it] = (uint32_t)(arr*10240 + row*80 + seg*16);
    }

    const int g = lane >> 3, r = lane & 7;
    const int wm = (wid & 3) * 32;
    const int wn = (wid >> 2) * 64;
    uint32_t aoff[2][2];
    #pragma unroll
    for (int mi = 0; mi < 2; ++mi) {
        const uint32_t base = (uint32_t)((wm + mi*16 + r + (g&1)*8)*80 + ((g>>1)*8)*2);
        aoff[0][mi] = sbm + base;
        aoff[1][mi] = sbm + 10240 + base;
    }
    uint32_t boff[2][4];
    #pragma unroll
    for (int p = 0; p < 4; ++p) {
        const uint32_t base = (uint32_t)((wn + p*16 + r + (g>>1)*8)*80 + ((g&1)*8)*2);
        boff[0][p] = sbm + 20480 + base;
        boff[1][p] = sbm + 30720 + base;
    }

    float acc[2][8][4] = {};
    uint4 v[8];

    #pragma unroll
    for (int it = 0; it < 8; ++it) v[it] = *(const uint4*)(gptr[it]);
    #pragma unroll
    for (int it = 0; it < 8; ++it) *(uint4*)(esm + soff[it]) = v[it];
    __syncthreads();

    #pragma unroll 1
    for (int kc = 0; kc < 16; ++kc) {
        const uint32_t stg = (uint32_t)(kc & 1) * EIN_STAGE;
        if (kc < 15) {
            const int kb = (kc + 1) * 32;
            #pragma unroll
            for (int it = 0; it < 8; ++it)
                v[it] = *(const uint4*)(gptr[it] + kb);
        }
        #pragma unroll
        for (int ks2 = 0; ks2 < 2; ++ks2) {
            const uint32_t off = stg + (uint32_t)ks2 * 32;
            uint32_t AH[2][4], AL[2][4], BH[4][4], BL[4][4];
            #pragma unroll
            for (int mi = 0; mi < 2; ++mi) {
                ldm4(AH[mi], aoff[0][mi] + off);
                ldm4(AL[mi], aoff[1][mi] + off);
            }
            #pragma unroll
            for (int p = 0; p < 4; ++p) {
                ldm4(BH[p], boff[0][p] + off);
                ldm4(BL[p], boff[1][p] + off);
            }
            #pragma unroll
            for (int mi = 0; mi < 2; ++mi)
                #pragma unroll
                for (int ni = 0; ni < 8; ++ni) {
                    const int p = ni >> 1, h = (ni & 1) * 2;
                    mma_bf16(acc[mi][ni], AH[mi], BH[p][h], BH[p][h+1]);
                    mma_bf16(acc[mi][ni], AH[mi], BL[p][h], BL[p][h+1]);
                    mma_bf16(acc[mi][ni], AL[mi], BH[p][h], BH[p][h+1]);
                }
        }
        if (kc < 15) {
            const uint32_t nstg = (uint32_t)((kc + 1) & 1) * EIN_STAGE;
            #pragma unroll
            for (int it = 0; it < 8; ++it)
                *(uint4*)(esm + nstg + soff[it]) = v[it];
            __syncthreads();
        }
    }

    __syncthreads();
    float* smT = (float*)esm;
    #pragma unroll
    for (int mi = 0; mi < 2; ++mi)
        #pragma unroll
        for (int ni = 0; ni < 8; ++ni) {
            const int m = wm + mi*16 + (lane >> 2);
            const int j = wn + ni*8 + (lane & 3)*2;
            smT[(j  )*129 + m    ] = acc[mi][ni][0];
            smT[(j+1)*129 + m    ] = acc[mi][ni][1];
            smT[(j  )*129 + m + 8] = acc[mi][ni][2];
            smT[(j+1)*129 + m + 8] = acc[mi][ni][3];
        }
    __syncthreads();

    float* gm = g_mix + (size_t)d * NN;
    #pragma unroll
    for (int it = 0; it < 16; ++it) {
        const int idx = it*256 + tid;
        const int j = idx >> 5, c4 = idx & 31;
        float4 o;
        o.x = smT[j*129 + c4*4 + 0];
        o.y = smT[j*129 + c4*4 + 1];
        o.z = smT[j*129 + c4*4 + 2];
        o.w = smT[j*129 + c4*4 + 3];
        *reinterpret_cast<float4*>(gm + (size_t)(j0 + j)*512 + i0 + c4*4) = o;
    }
}

// ---------------------------------------------------------------------------
// Kernel 3: out-LN (over d) * out_gate, then @ W_out + b_out — MMA version.
// Block = 128 rt rows (rt = j*512+i, fixed j), single g_mix read.
// ---------------------------------------------------------------------------
#define O_MIX   0                      // f32 [128][132] = 67584; reused as out stage
#define O_AH    67584
#define O_AL    102400
#define O_RED   137216                 // red[2][2][128] f32 = 2048
#define O_SMEM  139264

__global__ __launch_bounds__(256, 1) void out_mma_kernel(
    const float* __restrict__ gs, const float* __restrict__ gb,
    const float* __restrict__ bout, float* __restrict__ out)
{
    extern __shared__ __align__(16) char sm3[];
    const int tid  = threadIdx.x;
    const int lane = tid & 31;
    const int wid  = tid >> 5;
    const int rt0  = blockIdx.x * 128;     // rt = j*512 + i
    const int j    = rt0 >> 9;
    const int ibase = rt0 & 511;
    const uint32_t sb = smem_u32(sm3);

    float* mixbuf = (float*)(sm3 + O_MIX);     // [d][132]
    float* red    = (float*)(sm3 + O_RED);     // [2][2][128]

    const int rt_l = tid & 127;
    const int half = tid >> 7;                 // 0/1 -> d in [0,64) or [64,128)
    const int d0   = half * 64;

    // ---- pass 1: load g_mix -> smem, partial LN stats ----
    float s = 0.f, q = 0.f;
    #pragma unroll 8
    for (int dd = d0; dd < d0 + 64; ++dd) {
        float v = g_mix[(size_t)dd*NN + rt0 + rt_l];
        mixbuf[dd*132 + rt_l] = v;
        s += v; q += v*v;
    }
    red[half*128 + rt_l]       = s;
    red[256 + half*128 + rt_l] = q;
    __syncthreads();
    const float S = red[rt_l] + red[128 + rt_l];
    const float Q = red[256 + rt_l] + red[384 + rt_l];
    const float mu   = S * (1.f/128.f);
    const float rstd = rsqrtf(Q * (1.f/128.f) - mu*mu + 1e-6f);

    // ---- pass 2: gate & split into A (bf16 hi/lo, [rt][d] 272B rows) ----
    #pragma unroll 4
    for (int dd = d0; dd < d0 + 64; dd += 2) {
        float v0 = mixbuf[ dd     *132 + rt_l];
        float v1 = mixbuf[(dd + 1)*132 + rt_l];
        float o0 = g_og[(size_t) dd     *NN + rt0 + rt_l];
        float o1 = g_og[(size_t)(dd + 1)*NN + rt0 + rt_l];
        float g0 = ((v0 - mu)*rstd*__ldg(gs+dd)   + __ldg(gb+dd))   * o0;
        float g1 = ((v1 - mu)*rstd*__ldg(gs+dd+1) + __ldg(gb+dd+1)) * o1;
        uint32_t p0 = split_pack(g0), p1 = split_pack(g1);
        *(uint32_t*)(sm3 + O_AH + rt_l*272 + dd*2) = (p0 & 0xffffu) | (p1 << 16);
        *(uint32_t*)(sm3 + O_AL + rt_l*272 + dd*2) = (p0 >> 16) | (p1 & 0xffff0000u);
    }
    __syncthreads();

    // ---- MMA: [128 rt] x [128 c] x [128 d], Wout fragments via LDG ----
    const int g = lane >> 3, r = lane & 7;
    const int wm = (wid & 3) * 32;
    const int wn = (wid >> 2) * 64;
    uint32_t aoffH[2], aoffL[2];
    #pragma unroll
    for (int mi = 0; mi < 2; ++mi) {
        const uint32_t base = (uint32_t)((wm + mi*16 + r + (g&1)*8) * 272 + ((g>>1)*8)*2);
        aoffH[mi] = sb + O_AH + base;
        aoffL[mi] = sb + O_AL + base;
    }
    const uint4* __restrict__ fw = g_wfrag + 5 * 4096 + lane;
    const int pbase = wn >> 4;

    float acc[2][8][4] = {};
    #pragma unroll
    for (int kc = 0; kc < 8; ++kc) {
        uint32_t AH[2][4], AL[2][4];
        #pragma unroll
        for (int mi = 0; mi < 2; ++mi) {
            ldm4(AH[mi], aoffH[mi] + kc*32);
            ldm4(AL[mi], aoffL[mi] + kc*32);
        }
        #pragma unroll
        for (int p4 = 0; p4 < 4; ++p4) {
            const int fidx = ((kc*8 + pbase + p4) * 2) * 32;
            const uint4 bh = fw[fidx];
            const uint4 bl = fw[fidx + 32];
            #pragma unroll
            for (int ns = 0; ns < 2; ++ns) {
                const int ni = p4*2 + ns;
                const uint32_t h0 = ns ? bh.z : bh.x, h1 = ns ? bh.w : bh.y;
                const uint32_t l0 = ns ? bl.z : bl.x, l1 = ns ? bl.w : bl.y;
                #pragma unroll
                for (int mi = 0; mi < 2; ++mi) {
                    mma_bf16(acc[mi][ni], AH[mi], h0, h1);
                    mma_bf16(acc[mi][ni], AH[mi], l0, l1);
                    mma_bf16(acc[mi][ni], AL[mi], h0, h1);
                }
            }
        }
    }
    __syncthreads();   // mixbuf reads (pass 2) long done; reuse as out stage

    float* stagef = mixbuf;   // [row][132]
    #pragma unroll
    for (int mi = 0; mi < 2; ++mi)
        #pragma unroll
        for (int ni = 0; ni < 8; ++ni) {
            const int m0 = wm + mi*16 + (lane >> 2);
            const int n  = wn + ni*8 + (lane & 3)*2;
            const float b0 = __ldg(bout + n), b1 = __ldg(bout + n + 1);
            stagef[ m0   *132 + n    ] = acc[mi][ni][0] + b0;
            stagef[ m0   *132 + n + 1] = acc[mi][ni][1] + b1;
            stagef[(m0+8)*132 + n    ] = acc[mi][ni][2] + b0;
            stagef[(m0+8)*132 + n + 1] = acc[mi][ni][3] + b1;
        }
    __syncthreads();

    #pragma unroll
    for (int it = 0; it < 16; ++it) {
        const int idx = it * 256 + tid;        // 128 rows x 32 f4
        const int row = idx >> 5, c4 = idx & 31;
        float4 v;
        v.x = stagef[row*132 + c4*4 + 0];
        v.y = stagef[row*132 + c4*4 + 1];
        v.z = stagef[row*132 + c4*4 + 2];
        v.w = stagef[row*132 + c4*4 + 3];
        *reinterpret_cast<float4*>(
            out + ((size_t)(ibase + row)*512 + j)*DD + c4*4) = v;
    }
}

// ---------------------------------------------------------------------------
extern "C" void kernel_launch(void* const* d_in, const int* in_sizes, int n_in,
                              void* d_out, int out_size)
{
    const float* x    = (const float*)d_in[0];
    const float* mskp = (const float*)d_in[1];
    const float* nsc  = (const float*)d_in[2];
    const float* nbi  = (const float*)d_in[3];
    const float* Wl   = (const float*)d_in[4];
    const float* bl   = (const float*)d_in[5];
    const float* Wr   = (const float*)d_in[6];
    const float* br   = (const float*)d_in[7];
    const float* Wlg  = (const float*)d_in[8];
    const float* blg  = (const float*)d_in[9];
    const float* Wrg  = (const float*)d_in[10];
    const float* brg  = (const float*)d_in[11];
    const float* Wog  = (const float*)d_in[12];
    const float* bog  = (const float*)d_in[13];
    const float* gs   = (const float*)d_in[14];
    const float* gb   = (const float*)d_in[15];
    const float* Wout = (const float*)d_in[16];
    const float* bout = (const float*)d_in[17];
    float* out = (float*)d_out;

    cudaFuncSetAttribute(einsum_mma_kernel,
                         cudaFuncAttributeMaxDynamicSharedMemorySize, EIN_SMEM);
    cudaFuncSetAttribute(ln_proj_mma_kernel,
                         cudaFuncAttributeMaxDynamicSharedMemorySize, K1_SMEM);
    cudaFuncSetAttribute(out_mma_kernel,
                         cudaFuncAttributeMaxDynamicSharedMemorySize, O_SMEM);

    wprep_kernel<<<6, 256>>>(Wlg, Wl, Wrg, Wr, Wog, Wout);
    ln_proj_mma_kernel<<<2048, 256, K1_SMEM>>>(x, mskp, nsc, nbi,
                                               bl, br, blg, brg, bog);
    einsum_mma_kernel<<<dim3(16, 128), 256, EIN_SMEM>>>();
    out_mma_kernel<<<2048, 256, O_SMEM>>>(gs, gb, bout, out);
}

// round 6
// speedup vs baseline: 1.9947x; 1.4142x over previous
#include <cuda_runtime.h>
#include <cuda_bf16.h>
#include <math.h>
#include <stdint.h>

// Problem constants
#define NTOK 512
#define DD   128
#define NN   (NTOK*NTOK)

// Scratch (static __device__ arrays — no allocation allowed)
//   g_lh/g_ll [c][i*512+k]  left  hi/lo bf16  (K-major for MMA A)
//   g_rh/g_rl [c][j*512+k]  right hi/lo bf16  (K-major for MMA B)
//   g_og      [c][j*512+i]  sigmoid(out-gate) f32
//   g_mix     [d][j*512+i]  einsum result f32 (transposed)
//   g_wfrag   [w][kc][p][spl][lane] uint4 — B-fragment-ready weights
//             w: 0=Wlg 1=Wl 2=Wrg 3=Wr 4=Wog 5=Wout
__device__ __nv_bfloat16 g_lh[33554432];
__device__ __nv_bfloat16 g_ll[33554432];
__device__ __nv_bfloat16 g_rh[33554432];
__device__ __nv_bfloat16 g_rl[33554432];
__device__ float         g_og [33554432];
__device__ float         g_mix[33554432];
__device__ __align__(16) uint4 g_wfrag[6 * 4096];

// ---------------------------------------------------------------------------
// helpers
// ---------------------------------------------------------------------------
__device__ __forceinline__ uint32_t smem_u32(const void* p) {
    uint32_t a;
    asm("{ .reg .u64 t; cvta.to.shared.u64 t, %1; cvt.u32.u64 %0, t; }"
        : "=r"(a) : "l"(p));
    return a;
}

__device__ __forceinline__ void ldm4(uint32_t r[4], uint32_t addr) {
    asm volatile("ldmatrix.sync.aligned.m8n8.x4.shared.b16 {%0,%1,%2,%3}, [%4];"
                 : "=r"(r[0]), "=r"(r[1]), "=r"(r[2]), "=r"(r[3]) : "r"(addr));
}

__device__ __forceinline__ void mma_bf16(float acc[4], const uint32_t a[4],
                                         uint32_t b0, uint32_t b1) {
    asm volatile(
        "mma.sync.aligned.m16n8k16.row.col.f32.bf16.bf16.f32 "
        "{%0,%1,%2,%3}, {%4,%5,%6,%7}, {%8,%9}, {%0,%1,%2,%3};"
        : "+f"(acc[0]), "+f"(acc[1]), "+f"(acc[2]), "+f"(acc[3])
        : "r"(a[0]), "r"(a[1]), "r"(a[2]), "r"(a[3]), "r"(b0), "r"(b1));
}

__device__ __forceinline__ float sigmoidf_(float z) {
    return 1.f / (1.f + expf(-z));
}

__device__ __forceinline__ uint32_t split_pack(float v) {
    // low16 = hi bf16, high16 = lo bf16
    __nv_bfloat16 h = __float2bfloat16(v);
    __nv_bfloat16 l = __float2bfloat16(v - __bfloat162float(h));
    uint16_t hu = *(uint16_t*)&h, lu = *(uint16_t*)&l;
    return (uint32_t)hu | ((uint32_t)lu << 16);
}

// ---------------------------------------------------------------------------
// Kernel 0: weights -> B-fragment layout (hi/lo), register-ready for mma.sync.
// ---------------------------------------------------------------------------
__global__ void wprep_kernel(const float* __restrict__ W0, const float* __restrict__ W1,
                             const float* __restrict__ W2, const float* __restrict__ W3,
                             const float* __restrict__ W4, const float* __restrict__ W5)
{
    const float* W = (blockIdx.x == 0) ? W0 : (blockIdx.x == 1) ? W1 :
                     (blockIdx.x == 2) ? W2 : (blockIdx.x == 3) ? W3 :
                     (blockIdx.x == 4) ? W4 : W5;
    uint4* dst = g_wfrag + blockIdx.x * 4096;
    for (int idx = threadIdx.x; idx < 4096; idx += 256) {
        const int lane = idx & 31;
        const int spl  = (idx >> 5) & 1;
        const int p    = (idx >> 6) & 7;
        const int kc   = idx >> 9;
        const int nf = p * 16 + (lane >> 2);
        const int k0 = kc * 16 + 2 * (lane & 3);
        uint16_t e[8];
        #pragma unroll
        for (int q = 0; q < 8; ++q) {
            const int k = k0 + (q & 1) + ((q >> 1) & 1) * 8;
            const int n = nf + (q >> 2) * 8;
            const float v = W[k * 128 + n];
            __nv_bfloat16 h = __float2bfloat16(v);
            __nv_bfloat16 l = __float2bfloat16(v - __bfloat162float(h));
            e[q] = spl ? *(uint16_t*)&l : *(uint16_t*)&h;
        }
        uint4 o;
        o.x = (uint32_t)e[0] | ((uint32_t)e[1] << 16);
        o.y = (uint32_t)e[2] | ((uint32_t)e[3] << 16);
        o.z = (uint32_t)e[4] | ((uint32_t)e[5] << 16);
        o.w = (uint32_t)e[6] | ((uint32_t)e[7] << 16);
        dst[idx] = o;
    }
}

// ---------------------------------------------------------------------------
// Kernel 1: LayerNorm + 5 projections. 64-row blocks (2-3 CTAs/SM).
// 8 warps as 2m x 4n, warp tile 32x32. Value+gate fused; weights via LDG.
// ---------------------------------------------------------------------------
#define K1_AH   0
#define K1_AL   17408
#define K1_ST   34816          // stage: 64 x 129 u32/f32 = 33024
#define K1_MS   67840          // mask_s: 64 f32
#define K1_SMEM 68096

template<bool PAIR>   // true: value+gate pair; false: out-gate only
__device__ __forceinline__ void k1_pass2(
    char* sm1, uint32_t sb, int wv, int wg,
    const float* __restrict__ bv, const float* __restrict__ bg,
    int tid, int lane, int wm, int wn,
    __nv_bfloat16* dst_h, __nv_bfloat16* dst_l, float* dst_og, size_t gbase)
{
    const int g = lane >> 3, r = lane & 7;
    uint32_t aoffH[2], aoffL[2];
    #pragma unroll
    for (int mi = 0; mi < 2; ++mi) {
        const uint32_t base = (uint32_t)((wm + mi*16 + r + (g&1)*8) * 272 + ((g>>1)*8)*2);
        aoffH[mi] = sb + K1_AH + base;
        aoffL[mi] = sb + K1_AL + base;
    }
    const uint4* __restrict__ fv = g_wfrag + wv * 4096 + lane;
    const uint4* __restrict__ fg = g_wfrag + wg * 4096 + lane;
    const int pbase = wn >> 4;

    float accV[2][4][4] = {};
    float accG[PAIR ? 2 : 1][4][4] = {};

    #pragma unroll
    for (int kc = 0; kc < 8; ++kc) {
        uint32_t AH[2][4], AL[2][4];
        #pragma unroll
        for (int mi = 0; mi < 2; ++mi) {
            ldm4(AH[mi], aoffH[mi] + kc*32);
            ldm4(AL[mi], aoffL[mi] + kc*32);
        }
        #pragma unroll
        for (int p4 = 0; p4 < 2; ++p4) {
            const int fidx = ((kc*8 + pbase + p4) * 2) * 32;
            const uint4 bvh = fv[fidx];
            const uint4 bvl = fv[fidx + 32];
            uint4 bgh, bgl;
            if (PAIR) { bgh = fg[fidx]; bgl = fg[fidx + 32]; }
            #pragma unroll
            for (int ns = 0; ns < 2; ++ns) {
                const int ni = p4*2 + ns;
                const uint32_t v0 = ns ? bvh.z : bvh.x, v1 = ns ? bvh.w : bvh.y;
                const uint32_t l0 = ns ? bvl.z : bvl.x, l1 = ns ? bvl.w : bvl.y;
                #pragma unroll
                for (int mi = 0; mi < 2; ++mi) {
                    mma_bf16(accV[mi][ni], AH[mi], v0, v1);
                    mma_bf16(accV[mi][ni], AH[mi], l0, l1);
                    mma_bf16(accV[mi][ni], AL[mi], v0, v1);
                }
                if (PAIR) {
                    const uint32_t g0 = ns ? bgh.z : bgh.x, g1 = ns ? bgh.w : bgh.y;
                    const uint32_t m0 = ns ? bgl.z : bgl.x, m1 = ns ? bgl.w : bgl.y;
                    #pragma unroll
                    for (int mi = 0; mi < 2; ++mi) {
                        mma_bf16(accG[mi][ni], AH[mi], g0, g1);
                        mma_bf16(accG[mi][ni], AH[mi], m0, m1);
                        mma_bf16(accG[mi][ni], AL[mi], g0, g1);
                    }
                }
            }
        }
    }

    float*    stagef = (float*)(sm1 + K1_ST);
    uint32_t* stageu = (uint32_t*)(sm1 + K1_ST);
    const float* mask_s = (const float*)(sm1 + K1_MS);

    #pragma unroll
    for (int mi = 0; mi < 2; ++mi)
        #pragma unroll
        for (int ni = 0; ni < 4; ++ni) {
            const int m0 = wm + mi*16 + (lane >> 2);
            const int n  = wn + ni*8 + (lane & 3)*2;
            const float b0 = __ldg(bv + n), b1 = __ldg(bv + n + 1);
            float* a = accV[mi][ni];
            if (PAIR) {
                const float c0 = __ldg(bg + n), c1 = __ldg(bg + n + 1);
                const float* gacc = accG[mi][ni];
                const float mk0 = mask_s[m0], mk1 = mask_s[m0 + 8];
                stageu[ m0   *129 + n    ] = split_pack((a[0]+b0)*mk0*sigmoidf_(gacc[0]+c0));
                stageu[ m0   *129 + n + 1] = split_pack((a[1]+b1)*mk0*sigmoidf_(gacc[1]+c1));
                stageu[(m0+8)*129 + n    ] = split_pack((a[2]+b0)*mk1*sigmoidf_(gacc[2]+c0));
                stageu[(m0+8)*129 + n + 1] = split_pack((a[3]+b1)*mk1*sigmoidf_(gacc[3]+c1));
            } else {
                stagef[ m0   *129 + n    ] = sigmoidf_(a[0] + b0);
                stagef[ m0   *129 + n + 1] = sigmoidf_(a[1] + b1);
                stagef[(m0+8)*129 + n    ] = sigmoidf_(a[2] + b0);
                stagef[(m0+8)*129 + n + 1] = sigmoidf_(a[3] + b1);
            }
        }
    __syncthreads();

    if (PAIR) {
        #pragma unroll
        for (int it = 0; it < 16; ++it) {
            const int idx = it * 256 + tid;        // 4096 = 128c x 32 row-pairs
            const int c  = idx >> 5;
            const int rp = (idx & 31) * 2;
            const uint32_t u0 = stageu[ rp      * 129 + c];
            const uint32_t u1 = stageu[(rp + 1) * 129 + c];
            const size_t addr = (size_t)c * NN + gbase + rp;
            *(uint32_t*)(dst_h + addr) = (u0 & 0xffffu) | (u1 << 16);
            *(uint32_t*)(dst_l + addr) = (u0 >> 16) | (u1 & 0xffff0000u);
        }
    } else {
        #pragma unroll
        for (int it = 0; it < 32; ++it) {
            const int idx = it * 256 + tid;        // 8192 floats
            const int c = idx >> 6, rr = idx & 63;
            dst_og[(size_t)c * NN + gbase + rr] = stagef[rr * 129 + c];
        }
    }
    __syncthreads();
}

__global__ __launch_bounds__(256, 2) void ln_proj_mma_kernel(
    const float* __restrict__ x,   const float* __restrict__ msk,
    const float* __restrict__ nsc, const float* __restrict__ nbi,
    const float* __restrict__ bl,  const float* __restrict__ br,
    const float* __restrict__ blg, const float* __restrict__ brg,
    const float* __restrict__ bog)
{
    extern __shared__ __align__(16) char sm1[];
    const int tid  = threadIdx.x;
    const int lane = tid & 31;
    const int wid  = tid >> 5;
    const int n2   = blockIdx.x & 511;
    const int n1b  = (blockIdx.x >> 9) << 6;   // 64-row blocks
    const uint32_t sb = smem_u32(sm1);

    // ---- LayerNorm: 4 threads per row, 32 elems each; write bf16 hi/lo A ----
    {
        const int row = tid >> 2, sub = tid & 3;
        const float4* xr = reinterpret_cast<const float4*>(
                               x + ((size_t)(n1b + row) * 512 + n2) * DD) + sub * 8;
        float4 v[8];
        float s = 0.f, ss = 0.f;
        #pragma unroll
        for (int q = 0; q < 8; ++q) {
            v[q] = xr[q];
            s  += v[q].x + v[q].y + v[q].z + v[q].w;
            ss += v[q].x*v[q].x + v[q].y*v[q].y + v[q].z*v[q].z + v[q].w*v[q].w;
        }
        s  += __shfl_xor_sync(0xffffffffu, s, 1);
        ss += __shfl_xor_sync(0xffffffffu, ss, 1);
        s  += __shfl_xor_sync(0xffffffffu, s, 2);
        ss += __shfl_xor_sync(0xffffffffu, ss, 2);
        const float mu   = s * (1.f/128.f);
        const float var  = ss * (1.f/128.f) - mu*mu;
        const float rstd = rsqrtf(var + 1e-6f);
        #pragma unroll
        for (int q = 0; q < 8; ++q) {
            const int d0 = sub*32 + q*4;
            float a0 = (v[q].x - mu)*rstd*__ldg(&nsc[d0+0]) + __ldg(&nbi[d0+0]);
            float a1 = (v[q].y - mu)*rstd*__ldg(&nsc[d0+1]) + __ldg(&nbi[d0+1]);
            float a2 = (v[q].z - mu)*rstd*__ldg(&nsc[d0+2]) + __ldg(&nbi[d0+2]);
            float a3 = (v[q].w - mu)*rstd*__ldg(&nsc[d0+3]) + __ldg(&nbi[d0+3]);
            uint32_t p0 = split_pack(a0), p1 = split_pack(a1);
            uint32_t p2 = split_pack(a2), p3 = split_pack(a3);
            uint2 hw, lw;
            hw.x = (p0 & 0xffffu) | (p1 << 16);
            hw.y = (p2 & 0xffffu) | (p3 << 16);
            lw.x = (p0 >> 16) | (p1 & 0xffff0000u);
            lw.y = (p2 >> 16) | (p3 & 0xffff0000u);
            *(uint2*)(sm1 + K1_AH + row*272 + d0*2) = hw;
            *(uint2*)(sm1 + K1_AL + row*272 + d0*2) = lw;
        }
        if (sub == 0)
            ((float*)(sm1 + K1_MS))[row] = msk[n1b + row] * msk[n2];
    }
    __syncthreads();

    const int wm = (wid & 1) * 32;
    const int wn = (wid >> 1) * 32;
    const size_t gbase = (size_t)n2 * 512 + n1b;

    k1_pass2<true >(sm1, sb, 1, 0, bl,  blg, tid, lane, wm, wn, g_lh, g_ll, 0, gbase);
    k1_pass2<true >(sm1, sb, 3, 2, br,  brg, tid, lane, wm, wn, g_rh, g_rl, 0, gbase);
    k1_pass2<false>(sm1, sb, 4, 4, bog, bog, tid, lane, wm, wn, 0, 0, g_og, gbase);
}

// ---------------------------------------------------------------------------
// Kernel 2: einsum 'bkid,bkjd->bijd' via mma.sync bf16 (hi/lo split, 3 MMAs).
// (unchanged — known good)
// ---------------------------------------------------------------------------
#define EIN_STAGE  40960
#define EIN_SMEM   (2*EIN_STAGE)

__global__ __launch_bounds__(256) void einsum_mma_kernel()
{
    extern __shared__ __align__(16) char esm[];
    const int tid  = threadIdx.x;
    const int lane = tid & 31;
    const int wid  = tid >> 5;
    const int d    = blockIdx.y;
    const int i0   = (blockIdx.x & 3) * 128;
    const int j0   = (blockIdx.x >> 2) * 128;
    const uint32_t sbm = smem_u32(esm);

    const __nv_bfloat16* __restrict__ pAH = g_lh + (size_t)d*NN;
    const __nv_bfloat16* __restrict__ pAL = g_ll + (size_t)d*NN;
    const __nv_bfloat16* __restrict__ pBH = g_rh + (size_t)d*NN;
    const __nv_bfloat16* __restrict__ pBL = g_rl + (size_t)d*NN;

    const __nv_bfloat16* gptr[8];
    uint32_t soff[8];
    #pragma unroll
    for (int it = 0; it < 8; ++it) {
        const int idx = it*256 + tid;
        const int arr = idx >> 9;
        const int rem = idx & 511;
        const int row = rem >> 2;
        const int seg = rem & 3;
        const __nv_bfloat16* src =
            (arr == 0) ? pAH : (arr == 1) ? pAL : (arr == 2) ? pBH : pBL;
        const int r0 = (arr < 2) ? i0 : j0;
        gptr[it] = src + (size_t)(r0 + row)*512 + seg*8;
        soff[it] = (uint32_t)(arr*10240 + row*80 + seg*16);
    }

    const int g = lane >> 3, r = lane & 7;
    const int wm = (wid & 3) * 32;
    const int wn = (wid >> 2) * 64;
    uint32_t aoff[2][2];
    #pragma unroll
    for (int mi = 0; mi < 2; ++mi) {
        const uint32_t base = (uint32_t)((wm + mi*16 + r + (g&1)*8)*80 + ((g>>1)*8)*2);
        aoff[0][mi] = sbm + base;
        aoff[1][mi] = sbm + 10240 + base;
    }
    uint32_t boff[2][4];
    #pragma unroll
    for (int p = 0; p < 4; ++p) {
        const uint32_t base = (uint32_t)((wn + p*16 + r + (g>>1)*8)*80 + ((g&1)*8)*2);
        boff[0][p] = sbm + 20480 + base;
        boff[1][p] = sbm + 30720 + base;
    }

    float acc[2][8][4] = {};
    uint4 v[8];

    #pragma unroll
    for (int it = 0; it < 8; ++it) v[it] = *(const uint4*)(gptr[it]);
    #pragma unroll
    for (int it = 0; it < 8; ++it) *(uint4*)(esm + soff[it]) = v[it];
    __syncthreads();

    #pragma unroll 1
    for (int kc = 0; kc < 16; ++kc) {
        const uint32_t stg = (uint32_t)(kc & 1) * EIN_STAGE;
        if (kc < 15) {
            const int kb = (kc + 1) * 32;
            #pragma unroll
            for (int it = 0; it < 8; ++it)
                v[it] = *(const uint4*)(gptr[it] + kb);
        }
        #pragma unroll
        for (int ks2 = 0; ks2 < 2; ++ks2) {
            const uint32_t off = stg + (uint32_t)ks2 * 32;
            uint32_t AH[2][4], AL[2][4], BH[4][4], BL[4][4];
            #pragma unroll
            for (int mi = 0; mi < 2; ++mi) {
                ldm4(AH[mi], aoff[0][mi] + off);
                ldm4(AL[mi], aoff[1][mi] + off);
            }
            #pragma unroll
            for (int p = 0; p < 4; ++p) {
                ldm4(BH[p], boff[0][p] + off);
                ldm4(BL[p], boff[1][p] + off);
            }
            #pragma unroll
            for (int mi = 0; mi < 2; ++mi)
                #pragma unroll
                for (int ni = 0; ni < 8; ++ni) {
                    const int p = ni >> 1, h = (ni & 1) * 2;
                    mma_bf16(acc[mi][ni], AH[mi], BH[p][h], BH[p][h+1]);
                    mma_bf16(acc[mi][ni], AH[mi], BL[p][h], BL[p][h+1]);
                    mma_bf16(acc[mi][ni], AL[mi], BH[p][h], BH[p][h+1]);
                }
        }
        if (kc < 15) {
            const uint32_t nstg = (uint32_t)((kc + 1) & 1) * EIN_STAGE;
            #pragma unroll
            for (int it = 0; it < 8; ++it)
                *(uint4*)(esm + nstg + soff[it]) = v[it];
            __syncthreads();
        }
    }

    __syncthreads();
    float* smT = (float*)esm;
    #pragma unroll
    for (int mi = 0; mi < 2; ++mi)
        #pragma unroll
        for (int ni = 0; ni < 8; ++ni) {
            const int m = wm + mi*16 + (lane >> 2);
            const int j = wn + ni*8 + (lane & 3)*2;
            smT[(j  )*129 + m    ] = acc[mi][ni][0];
            smT[(j+1)*129 + m    ] = acc[mi][ni][1];
            smT[(j  )*129 + m + 8] = acc[mi][ni][2];
            smT[(j+1)*129 + m + 8] = acc[mi][ni][3];
        }
    __syncthreads();

    float* gm = g_mix + (size_t)d * NN;
    #pragma unroll
    for (int it = 0; it < 16; ++it) {
        const int idx = it*256 + tid;
        const int j = idx >> 5, c4 = idx & 31;
        float4 o;
        o.x = smT[j*129 + c4*4 + 0];
        o.y = smT[j*129 + c4*4 + 1];
        o.z = smT[j*129 + c4*4 + 2];
        o.w = smT[j*129 + c4*4 + 3];
        *reinterpret_cast<float4*>(gm + (size_t)(j0 + j)*512 + i0 + c4*4) = o;
    }
}

// ---------------------------------------------------------------------------
// Kernel 3: out-LN (over d) * out_gate, then @ W_out + b_out — MMA version.
// 64-row blocks (2-3 CTAs/SM), 8 warps 2m x 4n, warp tile 32x32.
// ---------------------------------------------------------------------------
#define O_MIX   0                      // f32 [128][68] = 34816; reused as out stage [64][132]
#define O_AH    34816
#define O_AL    52224
#define O_RED   69632                  // red[2][4][64] f32 = 2048
#define O_SMEM  71680

__global__ __launch_bounds__(256, 2) void out_mma_kernel(
    const float* __restrict__ gs, const float* __restrict__ gb,
    const float* __restrict__ bout, float* __restrict__ out)
{
    extern __shared__ __align__(16) char sm3[];
    const int tid  = threadIdx.x;
    const int lane = tid & 31;
    const int wid  = tid >> 5;
    const int rt0  = blockIdx.x * 64;      // rt = j*512 + i
    const int j    = rt0 >> 9;
    const int ibase = rt0 & 511;
    const uint32_t sb = smem_u32(sm3);

    float* mixbuf = (float*)(sm3 + O_MIX);     // [d][68]
    float* red    = (float*)(sm3 + O_RED);     // [2][4][64]

    const int rt_l = tid & 63;
    const int qtr  = tid >> 6;                 // 0..3 -> d quarter
    const int d0   = qtr * 32;

    // ---- pass 1: load g_mix -> smem, partial LN stats ----
    float s = 0.f, q = 0.f;
    #pragma unroll 8
    for (int dd = d0; dd < d0 + 32; ++dd) {
        float v = g_mix[(size_t)dd*NN + rt0 + rt_l];
        mixbuf[dd*68 + rt_l] = v;
        s += v; q += v*v;
    }
    red[qtr*64 + rt_l]       = s;
    red[256 + qtr*64 + rt_l] = q;
    __syncthreads();
    const float S = red[rt_l] + red[64 + rt_l] + red[128 + rt_l] + red[192 + rt_l];
    const float Q = red[256 + rt_l] + red[320 + rt_l] + red[384 + rt_l] + red[448 + rt_l];
    const float mu   = S * (1.f/128.f);
    const float rstd = rsqrtf(Q * (1.f/128.f) - mu*mu + 1e-6f);

    // ---- pass 2: gate & split into A (bf16 hi/lo, [rt][d] 272B rows) ----
    #pragma unroll 4
    for (int dd = d0; dd < d0 + 32; dd += 2) {
        float v0 = mixbuf[ dd     *68 + rt_l];
        float v1 = mixbuf[(dd + 1)*68 + rt_l];
        float o0 = g_og[(size_t) dd     *NN + rt0 + rt_l];
        float o1 = g_og[(size_t)(dd + 1)*NN + rt0 + rt_l];
        float g0 = ((v0 - mu)*rstd*__ldg(gs+dd)   + __ldg(gb+dd))   * o0;
        float g1 = ((v1 - mu)*rstd*__ldg(gs+dd+1) + __ldg(gb+dd+1)) * o1;
        uint32_t p0 = split_pack(g0), p1 = split_pack(g1);
        *(uint32_t*)(sm3 + O_AH + rt_l*272 + dd*2) = (p0 & 0xffffu) | (p1 << 16);
        *(uint32_t*)(sm3 + O_AL + rt_l*272 + dd*2) = (p0 >> 16) | (p1 & 0xffff0000u);
    }
    __syncthreads();

    // ---- MMA: [64 rt] x [128 c] x [128 d], Wout fragments via LDG ----
    const int g = lane >> 3, r = lane & 7;
    const int wm = (wid & 1) * 32;
    const int wn = (wid >> 1) * 32;
    uint32_t aoffH[2], aoffL[2];
    #pragma unroll
    for (int mi = 0; mi < 2; ++mi) {
        const uint32_t base = (uint32_t)((wm + mi*16 + r + (g&1)*8) * 272 + ((g>>1)*8)*2);
        aoffH[mi] = sb + O_AH + base;
        aoffL[mi] = sb + O_AL + base;
    }
    const uint4* __restrict__ fw = g_wfrag + 5 * 4096 + lane;
    const int pbase = wn >> 4;

    float acc[2][4][4] = {};
    #pragma unroll
    for (int kc = 0; kc < 8; ++kc) {
        uint32_t AH[2][4], AL[2][4];
        #pragma unroll
        for (int mi = 0; mi < 2; ++mi) {
            ldm4(AH[mi], aoffH[mi] + kc*32);
            ldm4(AL[mi], aoffL[mi] + kc*32);
        }
        #pragma unroll
        for (int p4 = 0; p4 < 2; ++p4) {
            const int fidx = ((kc*8 + pbase + p4) * 2) * 32;
            const uint4 bh = fw[fidx];
            const uint4 bl = fw[fidx + 32];
            #pragma unroll
            for (int ns = 0; ns < 2; ++ns) {
                const int ni = p4*2 + ns;
                const uint32_t h0 = ns ? bh.z : bh.x, h1 = ns ? bh.w : bh.y;
                const uint32_t l0 = ns ? bl.z : bl.x, l1 = ns ? bl.w : bl.y;
                #pragma unroll
                for (int mi = 0; mi < 2; ++mi) {
                    mma_bf16(acc[mi][ni], AH[mi], h0, h1);
                    mma_bf16(acc[mi][ni], AH[mi], l0, l1);
                    mma_bf16(acc[mi][ni], AL[mi], h0, h1);
                }
            }
        }
    }
    __syncthreads();   // A reads done; reuse mixbuf as out stage [64][132]

    float* stagef = mixbuf;
    #pragma unroll
    for (int mi = 0; mi < 2; ++mi)
        #pragma unroll
        for (int ni = 0; ni < 4; ++ni) {
            const int m0 = wm + mi*16 + (lane >> 2);
            const int n  = wn + ni*8 + (lane & 3)*2;
            const float b0 = __ldg(bout + n), b1 = __ldg(bout + n + 1);
            stagef[ m0   *132 + n    ] = acc[mi][ni][0] + b0;
            stagef[ m0   *132 + n + 1] = acc[mi][ni][1] + b1;
            stagef[(m0+8)*132 + n    ] = acc[mi][ni][2] + b0;
            stagef[(m0+8)*132 + n + 1] = acc[mi][ni][3] + b1;
        }
    __syncthreads();

    #pragma unroll
    for (int it = 0; it < 8; ++it) {
        const int idx = it * 256 + tid;        // 64 rows x 32 f4
        const int row = idx >> 5, c4 = idx & 31;
        float4 v;
        v.x = stagef[row*132 + c4*4 + 0];
        v.y = stagef[row*132 + c4*4 + 1];
        v.z = stagef[row*132 + c4*4 + 2];
        v.w = stagef[row*132 + c4*4 + 3];
        *reinterpret_cast<float4*>(
            out + ((size_t)(ibase + row)*512 + j)*DD + c4*4) = v;
    }
}

// ---------------------------------------------------------------------------
extern "C" void kernel_launch(void* const* d_in, const int* in_sizes, int n_in,
                              void* d_out, int out_size)
{
    const float* x    = (const float*)d_in[0];
    const float* mskp = (const float*)d_in[1];
    const float* nsc  = (const float*)d_in[2];
    const float* nbi  = (const float*)d_in[3];
    const float* Wl   = (const float*)d_in[4];
    const float* bl   = (const float*)d_in[5];
    const float* Wr   = (const float*)d_in[6];
    const float* br   = (const float*)d_in[7];
    const float* Wlg  = (const float*)d_in[8];
    const float* blg  = (const float*)d_in[9];
    const float* Wrg  = (const float*)d_in[10];
    const float* brg  = (const float*)d_in[11];
    const float* Wog  = (const float*)d_in[12];
    const float* bog  = (const float*)d_in[13];
    const float* gs   = (const float*)d_in[14];
    const float* gb   = (const float*)d_in[15];
    const float* Wout = (const float*)d_in[16];
    const float* bout = (const float*)d_in[17];
    float* out = (float*)d_out;

    cudaFuncSetAttribute(einsum_mma_kernel,
                         cudaFuncAttributeMaxDynamicSharedMemorySize, EIN_SMEM);
    cudaFuncSetAttribute(ln_proj_mma_kernel,
                         cudaFuncAttributeMaxDynamicSharedMemorySize, K1_SMEM);
    cudaFuncSetAttribute(out_mma_kernel,
                         cudaFuncAttributeMaxDynamicSharedMemorySize, O_SMEM);

    wprep_kernel<<<6, 256>>>(Wlg, Wl, Wrg, Wr, Wog, Wout);
    ln_proj_mma_kernel<<<4096, 256, K1_SMEM>>>(x, mskp, nsc, nbi,
                                               bl, br, blg, brg, bog);
    einsum_mma_kernel<<<dim3(16, 128), 256, EIN_SMEM>>>();
    out_mma_kernel<<<4096, 256, O_SMEM>>>(gs, gb, bout, out);
}

// round 7
// speedup vs baseline: 2.2301x; 1.1180x over previous
#include <cuda_runtime.h>
#include <cuda_bf16.h>
#include <cuda_fp16.h>
#include <math.h>
#include <stdint.h>

// Problem constants
#define NTOK 512
#define DD   128
#define NN   (NTOK*NTOK)

// Scratch (static __device__ arrays — no allocation allowed)
__device__ __nv_bfloat16 g_lh[33554432];
__device__ __nv_bfloat16 g_ll[33554432];
__device__ __nv_bfloat16 g_rh[33554432];
__device__ __nv_bfloat16 g_rl[33554432];
__device__ __half        g_og [33554432];
__device__ float         g_mix[33554432];
__device__ __align__(16) uint4 g_wfrag[6 * 4096];

// ---------------------------------------------------------------------------
// helpers
// ---------------------------------------------------------------------------
__device__ __forceinline__ uint32_t smem_u32(const void* p) {
    uint32_t a;
    asm("{ .reg .u64 t; cvta.to.shared.u64 t, %1; cvt.u32.u64 %0, t; }"
        : "=r"(a) : "l"(p));
    return a;
}

__device__ __forceinline__ void ldm4(uint32_t r[4], uint32_t addr) {
    asm volatile("ldmatrix.sync.aligned.m8n8.x4.shared.b16 {%0,%1,%2,%3}, [%4];"
                 : "=r"(r[0]), "=r"(r[1]), "=r"(r[2]), "=r"(r[3]) : "r"(addr));
}

__device__ __forceinline__ void mma_bf16(float acc[4], const uint32_t a[4],
                                         uint32_t b0, uint32_t b1) {
    asm volatile(
        "mma.sync.aligned.m16n8k16.row.col.f32.bf16.bf16.f32 "
        "{%0,%1,%2,%3}, {%4,%5,%6,%7}, {%8,%9}, {%0,%1,%2,%3};"
        : "+f"(acc[0]), "+f"(acc[1]), "+f"(acc[2]), "+f"(acc[3])
        : "r"(a[0]), "r"(a[1]), "r"(a[2]), "r"(a[3]), "r"(b0), "r"(b1));
}

__device__ __forceinline__ float sigmoidf_(float z) {
    return 1.f / (1.f + expf(-z));
}

__device__ __forceinline__ uint32_t split_pack(float v) {
    __nv_bfloat16 h = __float2bfloat16(v);
    __nv_bfloat16 l = __float2bfloat16(v - __bfloat162float(h));
    uint16_t hu = *(uint16_t*)&h, lu = *(uint16_t*)&l;
    return (uint32_t)hu | ((uint32_t)lu << 16);
}

// ---------------------------------------------------------------------------
// Kernel 0: weights -> B-fragment layout (hi/lo), register-ready for mma.sync.
// ---------------------------------------------------------------------------
__global__ void wprep_kernel(const float* __restrict__ W0, const float* __restrict__ W1,
                             const float* __restrict__ W2, const float* __restrict__ W3,
                             const float* __restrict__ W4, const float* __restrict__ W5)
{
    const float* W = (blockIdx.x == 0) ? W0 : (blockIdx.x == 1) ? W1 :
                     (blockIdx.x == 2) ? W2 : (blockIdx.x == 3) ? W3 :
                     (blockIdx.x == 4) ? W4 : W5;
    uint4* dst = g_wfrag + blockIdx.x * 4096;
    for (int idx = threadIdx.x; idx < 4096; idx += 256) {
        const int lane = idx & 31;
        const int spl  = (idx >> 5) & 1;
        const int p    = (idx >> 6) & 7;
        const int kc   = idx >> 9;
        const int nf = p * 16 + (lane >> 2);
        const int k0 = kc * 16 + 2 * (lane & 3);
        uint16_t e[8];
        #pragma unroll
        for (int q = 0; q < 8; ++q) {
            const int k = k0 + (q & 1) + ((q >> 1) & 1) * 8;
            const int n = nf + (q >> 2) * 8;
            const float v = W[k * 128 + n];
            __nv_bfloat16 h = __float2bfloat16(v);
            __nv_bfloat16 l = __float2bfloat16(v - __bfloat162float(h));
            e[q] = spl ? *(uint16_t*)&l : *(uint16_t*)&h;
        }
        uint4 o;
        o.x = (uint32_t)e[0] | ((uint32_t)e[1] << 16);
        o.y = (uint32_t)e[2] | ((uint32_t)e[3] << 16);
        o.z = (uint32_t)e[4] | ((uint32_t)e[5] << 16);
        o.w = (uint32_t)e[6] | ((uint32_t)e[7] << 16);
        dst[idx] = o;
    }
}

// ---------------------------------------------------------------------------
// Kernel 1: LayerNorm + 5 projections. 64-row blocks. Value+gate fused.
// ---------------------------------------------------------------------------
#define K1_AH   0
#define K1_AL   17408
#define K1_ST   34816
#define K1_MS   67840
#define K1_SMEM 68096

template<bool PAIR>
__device__ __forceinline__ void k1_pass2(
    char* sm1, uint32_t sb, int wv, int wg,
    const float* __restrict__ bv, const float* __restrict__ bg,
    int tid, int lane, int wm, int wn,
    __nv_bfloat16* dst_h, __nv_bfloat16* dst_l, __half* dst_og, size_t gbase)
{
    const int g = lane >> 3, r = lane & 7;
    uint32_t aoffH[2], aoffL[2];
    #pragma unroll
    for (int mi = 0; mi < 2; ++mi) {
        const uint32_t base = (uint32_t)((wm + mi*16 + r + (g&1)*8) * 272 + ((g>>1)*8)*2);
        aoffH[mi] = sb + K1_AH + base;
        aoffL[mi] = sb + K1_AL + base;
    }
    const uint4* __restrict__ fv = g_wfrag + wv * 4096 + lane;
    const uint4* __restrict__ fg = g_wfrag + wg * 4096 + lane;
    const int pbase = wn >> 4;

    float accV[2][4][4] = {};
    float accG[PAIR ? 2 : 1][4][4] = {};

    #pragma unroll
    for (int kc = 0; kc < 8; ++kc) {
        uint32_t AH[2][4], AL[2][4];
        #pragma unroll
        for (int mi = 0; mi < 2; ++mi) {
            ldm4(AH[mi], aoffH[mi] + kc*32);
            ldm4(AL[mi], aoffL[mi] + kc*32);
        }
        #pragma unroll
        for (int p4 = 0; p4 < 2; ++p4) {
            const int fidx = ((kc*8 + pbase + p4) * 2) * 32;
            const uint4 bvh = fv[fidx];
            const uint4 bvl = fv[fidx + 32];
            uint4 bgh, bgl;
            if (PAIR) { bgh = fg[fidx]; bgl = fg[fidx + 32]; }
            #pragma unroll
            for (int ns = 0; ns < 2; ++ns) {
                const int ni = p4*2 + ns;
                const uint32_t v0 = ns ? bvh.z : bvh.x, v1 = ns ? bvh.w : bvh.y;
                const uint32_t l0 = ns ? bvl.z : bvl.x, l1 = ns ? bvl.w : bvl.y;
                #pragma unroll
                for (int mi = 0; mi < 2; ++mi) {
                    mma_bf16(accV[mi][ni], AH[mi], v0, v1);
                    mma_bf16(accV[mi][ni], AH[mi], l0, l1);
                    mma_bf16(accV[mi][ni], AL[mi], v0, v1);
                }
                if (PAIR) {
                    const uint32_t g0 = ns ? bgh.z : bgh.x, g1 = ns ? bgh.w : bgh.y;
                    const uint32_t m0 = ns ? bgl.z : bgl.x, m1 = ns ? bgl.w : bgl.y;
                    #pragma unroll
                    for (int mi = 0; mi < 2; ++mi) {
                        mma_bf16(accG[mi][ni], AH[mi], g0, g1);
                        mma_bf16(accG[mi][ni], AH[mi], m0, m1);
                        mma_bf16(accG[mi][ni], AL[mi], g0, g1);
                    }
                }
            }
        }
    }

    float*    stagef = (float*)(sm1 + K1_ST);
    uint32_t* stageu = (uint32_t*)(sm1 + K1_ST);
    const float* mask_s = (const float*)(sm1 + K1_MS);

    #pragma unroll
    for (int mi = 0; mi < 2; ++mi)
        #pragma unroll
        for (int ni = 0; ni < 4; ++ni) {
            const int m0 = wm + mi*16 + (lane >> 2);
            const int n  = wn + ni*8 + (lane & 3)*2;
            const float b0 = __ldg(bv + n), b1 = __ldg(bv + n + 1);
            float* a = accV[mi][ni];
            if (PAIR) {
                const float c0 = __ldg(bg + n), c1 = __ldg(bg + n + 1);
                const float* gacc = accG[mi][ni];
                const float mk0 = mask_s[m0], mk1 = mask_s[m0 + 8];
                stageu[ m0   *129 + n    ] = split_pack((a[0]+b0)*mk0*sigmoidf_(gacc[0]+c0));
                stageu[ m0   *129 + n + 1] = split_pack((a[1]+b1)*mk0*sigmoidf_(gacc[1]+c1));
                stageu[(m0+8)*129 + n    ] = split_pack((a[2]+b0)*mk1*sigmoidf_(gacc[2]+c0));
                stageu[(m0+8)*129 + n + 1] = split_pack((a[3]+b1)*mk1*sigmoidf_(gacc[3]+c1));
            } else {
                stagef[ m0   *129 + n    ] = sigmoidf_(a[0] + b0);
                stagef[ m0   *129 + n + 1] = sigmoidf_(a[1] + b1);
                stagef[(m0+8)*129 + n    ] = sigmoidf_(a[2] + b0);
                stagef[(m0+8)*129 + n + 1] = sigmoidf_(a[3] + b1);
            }
        }
    __syncthreads();

    if (PAIR) {
        #pragma unroll
        for (int it = 0; it < 16; ++it) {
            const int idx = it * 256 + tid;
            const int c  = idx >> 5;
            const int rp = (idx & 31) * 2;
            const uint32_t u0 = stageu[ rp      * 129 + c];
            const uint32_t u1 = stageu[(rp + 1) * 129 + c];
            const size_t addr = (size_t)c * NN + gbase + rp;
            *(uint32_t*)(dst_h + addr) = (u0 & 0xffffu) | (u1 << 16);
            *(uint32_t*)(dst_l + addr) = (u0 >> 16) | (u1 & 0xffff0000u);
        }
    } else {
        #pragma unroll
        for (int it = 0; it < 16; ++it) {
            const int idx = it * 256 + tid;
            const int c  = idx >> 5;
            const int rp = (idx & 31) * 2;
            __half2 h2 = __floats2half2_rn(stagef[rp*129 + c], stagef[(rp+1)*129 + c]);
            *(__half2*)(dst_og + (size_t)c * NN + gbase + rp) = h2;
        }
    }
    __syncthreads();
}

__global__ __launch_bounds__(256, 2) void ln_proj_mma_kernel(
    const float* __restrict__ x,   const float* __restrict__ msk,
    const float* __restrict__ nsc, const float* __restrict__ nbi,
    const float* __restrict__ bl,  const float* __restrict__ br,
    const float* __restrict__ blg, const float* __restrict__ brg,
    const float* __restrict__ bog)
{
    extern __shared__ __align__(16) char sm1[];
    const int tid  = threadIdx.x;
    const int lane = tid & 31;
    const int wid  = tid >> 5;
    const int n2   = blockIdx.x & 511;
    const int n1b  = (blockIdx.x >> 9) << 6;
    const uint32_t sb = smem_u32(sm1);

    {
        const int row = tid >> 2, sub = tid & 3;
        const float4* xr = reinterpret_cast<const float4*>(
                               x + ((size_t)(n1b + row) * 512 + n2) * DD) + sub * 8;
        float4 v[8];
        float s = 0.f, ss = 0.f;
        #pragma unroll
        for (int q = 0; q < 8; ++q) {
            v[q] = xr[q];
            s  += v[q].x + v[q].y + v[q].z + v[q].w;
            ss += v[q].x*v[q].x + v[q].y*v[q].y + v[q].z*v[q].z + v[q].w*v[q].w;
        }
        s  += __shfl_xor_sync(0xffffffffu, s, 1);
        ss += __shfl_xor_sync(0xffffffffu, ss, 1);
        s  += __shfl_xor_sync(0xffffffffu, s, 2);
        ss += __shfl_xor_sync(0xffffffffu, ss, 2);
        const float mu   = s * (1.f/128.f);
        const float var  = ss * (1.f/128.f) - mu*mu;
        const float rstd = rsqrtf(var + 1e-6f);
        #pragma unroll
        for (int q = 0; q < 8; ++q) {
            const int d0 = sub*32 + q*4;
            float a0 = (v[q].x - mu)*rstd*__ldg(&nsc[d0+0]) + __ldg(&nbi[d0+0]);
            float a1 = (v[q].y - mu)*rstd*__ldg(&nsc[d0+1]) + __ldg(&nbi[d0+1]);
            float a2 = (v[q].z - mu)*rstd*__ldg(&nsc[d0+2]) + __ldg(&nbi[d0+2]);
            float a3 = (v[q].w - mu)*rstd*__ldg(&nsc[d0+3]) + __ldg(&nbi[d0+3]);
            uint32_t p0 = split_pack(a0), p1 = split_pack(a1);
            uint32_t p2 = split_pack(a2), p3 = split_pack(a3);
            uint2 hw, lw;
            hw.x = (p0 & 0xffffu) | (p1 << 16);
            hw.y = (p2 & 0xffffu) | (p3 << 16);
            lw.x = (p0 >> 16) | (p1 & 0xffff0000u);
            lw.y = (p2 >> 16) | (p3 & 0xffff0000u);
            *(uint2*)(sm1 + K1_AH + row*272 + d0*2) = hw;
            *(uint2*)(sm1 + K1_AL + row*272 + d0*2) = lw;
        }
        if (sub == 0)
            ((float*)(sm1 + K1_MS))[row] = msk[n1b + row] * msk[n2];
    }
    __syncthreads();

    const int wm = (wid & 1) * 32;
    const int wn = (wid >> 1) * 32;
    const size_t gbase = (size_t)n2 * 512 + n1b;

    k1_pass2<true >(sm1, sb, 1, 0, bl,  blg, tid, lane, wm, wn, g_lh, g_ll, 0, gbase);
    k1_pass2<true >(sm1, sb, 3, 2, br,  brg, tid, lane, wm, wn, g_rh, g_rl, 0, gbase);
    k1_pass2<false>(sm1, sb, 4, 4, bog, bog, tid, lane, wm, wn, 0, 0, g_og, gbase);
}

// ---------------------------------------------------------------------------
// Kernel 2: einsum via mma.sync bf16 (hi/lo split, 3 MMAs). 128x64 tiles,
// 2 CTAs/SM. 8 warps 4m x 2n, warp tile 32x32.
// ---------------------------------------------------------------------------
#define E2_STAGE 30720
#define E2_SMEM  61440

__global__ __launch_bounds__(256, 2) void einsum_mma_kernel()
{
    extern __shared__ __align__(16) char esm[];
    const int tid  = threadIdx.x;
    const int lane = tid & 31;
    const int wid  = tid >> 5;
    const int d    = blockIdx.y;
    const int i0   = (blockIdx.x & 3) * 128;
    const int j0   = (blockIdx.x >> 2) * 64;
    const uint32_t sbm = smem_u32(esm);

    const __nv_bfloat16* __restrict__ pAH = g_lh + (size_t)d*NN;
    const __nv_bfloat16* __restrict__ pAL = g_ll + (size_t)d*NN;
    const __nv_bfloat16* __restrict__ pBH = g_rh + (size_t)d*NN;
    const __nv_bfloat16* __restrict__ pBL = g_rl + (size_t)d*NN;

    // chunk loads: AH 128r, AL 128r, BH 64r, BL 64r; 384 rows x 64B = 6x256x16B
    const __nv_bfloat16* gptr[6];
    uint32_t soff[6];
    #pragma unroll
    for (int it = 0; it < 6; ++it) {
        int arr, rem;
        if (it < 4) { arr = it >> 1; rem = (it & 1) * 256 + tid; }
        else        { arr = it - 2;  rem = tid; }
        const int row = rem >> 2, seg = rem & 3;
        const __nv_bfloat16* src =
            (arr == 0) ? pAH : (arr == 1) ? pAL : (arr == 2) ? pBH : pBL;
        const int r0 = (arr < 2) ? i0 : j0;
        const uint32_t ab = (arr == 0) ? 0u : (arr == 1) ? 10240u :
                            (arr == 2) ? 20480u : 25600u;
        gptr[it] = src + (size_t)(r0 + row)*512 + seg*8;
        soff[it] = ab + (uint32_t)(row*80 + seg*16);
    }

    const int g = lane >> 3, r = lane & 7;
    const int wm = (wid & 3) * 32;
    const int wn = (wid >> 2) * 32;
    uint32_t aoff[2][2], boff[2][2];
    #pragma unroll
    for (int mi = 0; mi < 2; ++mi) {
        const uint32_t base = (uint32_t)((wm + mi*16 + r + (g&1)*8)*80 + ((g>>1)*8)*2);
        aoff[0][mi] = sbm + base;
        aoff[1][mi] = sbm + 10240 + base;
    }
    #pragma unroll
    for (int p = 0; p < 2; ++p) {
        const uint32_t base = (uint32_t)((wn + p*16 + r + (g>>1)*8)*80 + ((g&1)*8)*2);
        boff[0][p] = sbm + 20480 + base;
        boff[1][p] = sbm + 25600 + base;
    }

    float acc[2][4][4] = {};
    uint4 v[6];

    #pragma unroll
    for (int it = 0; it < 6; ++it) v[it] = *(const uint4*)(gptr[it]);
    #pragma unroll
    for (int it = 0; it < 6; ++it) *(uint4*)(esm + soff[it]) = v[it];
    __syncthreads();

    #pragma unroll 1
    for (int kc = 0; kc < 16; ++kc) {
        const uint32_t stg = (uint32_t)(kc & 1) * E2_STAGE;
        if (kc < 15) {
            const int kb = (kc + 1) * 32;
            #pragma unroll
            for (int it = 0; it < 6; ++it)
                v[it] = *(const uint4*)(gptr[it] + kb);
        }
        #pragma unroll
        for (int ks2 = 0; ks2 < 2; ++ks2) {
            const uint32_t off = stg + (uint32_t)ks2 * 32;
            uint32_t AH[2][4], AL[2][4], BH[2][4], BL[2][4];
            #pragma unroll
            for (int mi = 0; mi < 2; ++mi) {
                ldm4(AH[mi], aoff[0][mi] + off);
                ldm4(AL[mi], aoff[1][mi] + off);
            }
            #pragma unroll
            for (int p = 0; p < 2; ++p) {
                ldm4(BH[p], boff[0][p] + off);
                ldm4(BL[p], boff[1][p] + off);
            }
            #pragma unroll
            for (int mi = 0; mi < 2; ++mi)
                #pragma unroll
                for (int ni = 0; ni < 4; ++ni) {
                    const int p = ni >> 1, h = (ni & 1) * 2;
                    mma_bf16(acc[mi][ni], AH[mi], BH[p][h], BH[p][h+1]);
                    mma_bf16(acc[mi][ni], AH[mi], BL[p][h], BL[p][h+1]);
                    mma_bf16(acc[mi][ni], AL[mi], BH[p][h], BH[p][h+1]);
                }
        }
        if (kc < 15) {
            const uint32_t nstg = (uint32_t)((kc + 1) & 1) * E2_STAGE;
            #pragma unroll
            for (int it = 0; it < 6; ++it)
                *(uint4*)(esm + nstg + soff[it]) = v[it];
            __syncthreads();
        }
    }

    __syncthreads();
    float* smT = (float*)esm;   // [64][132]
    #pragma unroll
    for (int mi = 0; mi < 2; ++mi)
        #pragma unroll
        for (int ni = 0; ni < 4; ++ni) {
            const int m = wm + mi*16 + (lane >> 2);
            const int j = wn + ni*8 + (lane & 3)*2;
            smT[(j  )*132 + m    ] = acc[mi][ni][0];
            smT[(j+1)*132 + m    ] = acc[mi][ni][1];
            smT[(j  )*132 + m + 8] = acc[mi][ni][2];
            smT[(j+1)*132 + m + 8] = acc[mi][ni][3];
        }
    __syncthreads();

    float* gm = g_mix + (size_t)d * NN;
    #pragma unroll
    for (int it = 0; it < 8; ++it) {
        const int idx = it*256 + tid;      // 64 rows x 32 f4
        const int j = idx >> 5, c4 = idx & 31;
        float4 o;
        o.x = smT[j*132 + c4*4 + 0];
        o.y = smT[j*132 + c4*4 + 1];
        o.z = smT[j*132 + c4*4 + 2];
        o.w = smT[j*132 + c4*4 + 3];
        *reinterpret_cast<float4*>(gm + (size_t)(j0 + j)*512 + i0 + c4*4) = o;
    }
}

// ---------------------------------------------------------------------------
// Kernel 3: out-LN (over d) * out_gate, then @ W_out + b_out — MMA version.
// 64-row blocks, 3 CTAs/SM target.
// ---------------------------------------------------------------------------
#define O_MIX   0
#define O_AH    34816
#define O_AL    52224
#define O_RED   69632
#define O_SMEM  71680

__global__ __launch_bounds__(256, 3) void out_mma_kernel(
    const float* __restrict__ gs, const float* __restrict__ gb,
    const float* __restrict__ bout, float* __restrict__ out)
{
    extern __shared__ __align__(16) char sm3[];
    const int tid  = threadIdx.x;
    const int lane = tid & 31;
    const int wid  = tid >> 5;
    const int rt0  = blockIdx.x * 64;
    const int j    = rt0 >> 9;
    const int ibase = rt0 & 511;
    const uint32_t sb = smem_u32(sm3);

    float* mixbuf = (float*)(sm3 + O_MIX);     // [d][68]
    float* red    = (float*)(sm3 + O_RED);

    const int rt_l = tid & 63;
    const int qtr  = tid >> 6;
    const int d0   = qtr * 32;

    float s = 0.f, q = 0.f;
    #pragma unroll 8
    for (int dd = d0; dd < d0 + 32; ++dd) {
        float v = g_mix[(size_t)dd*NN + rt0 + rt_l];
        mixbuf[dd*68 + rt_l] = v;
        s += v; q += v*v;
    }
    red[qtr*64 + rt_l]       = s;
    red[256 + qtr*64 + rt_l] = q;
    __syncthreads();
    const float S = red[rt_l] + red[64 + rt_l] + red[128 + rt_l] + red[192 + rt_l];
    const float Q = red[256 + rt_l] + red[320 + rt_l] + red[384 + rt_l] + red[448 + rt_l];
    const float mu   = S * (1.f/128.f);
    const float rstd = rsqrtf(Q * (1.f/128.f) - mu*mu + 1e-6f);

    #pragma unroll 4
    for (int dd = d0; dd < d0 + 32; dd += 2) {
        float v0 = mixbuf[ dd     *68 + rt_l];
        float v1 = mixbuf[(dd + 1)*68 + rt_l];
        float o0 = __half2float(g_og[(size_t) dd     *NN + rt0 + rt_l]);
        float o1 = __half2float(g_og[(size_t)(dd + 1)*NN + rt0 + rt_l]);
        float g0 = ((v0 - mu)*rstd*__ldg(gs+dd)   + __ldg(gb+dd))   * o0;
        float g1 = ((v1 - mu)*rstd*__ldg(gs+dd+1) + __ldg(gb+dd+1)) * o1;
        uint32_t p0 = split_pack(g0), p1 = split_pack(g1);
        *(uint32_t*)(sm3 + O_AH + rt_l*272 + dd*2) = (p0 & 0xffffu) | (p1 << 16);
        *(uint32_t*)(sm3 + O_AL + rt_l*272 + dd*2) = (p0 >> 16) | (p1 & 0xffff0000u);
    }
    __syncthreads();

    const int g = lane >> 3, r = lane & 7;
    const int wm = (wid & 1) * 32;
    const int wn = (wid >> 1) * 32;
    uint32_t aoffH[2], aoffL[2];
    #pragma unroll
    for (int mi = 0; mi < 2; ++mi) {
        const uint32_t base = (uint32_t)((wm + mi*16 + r + (g&1)*8) * 272 + ((g>>1)*8)*2);
        aoffH[mi] = sb + O_AH + base;
        aoffL[mi] = sb + O_AL + base;
    }
    const uint4* __restrict__ fw = g_wfrag + 5 * 4096 + lane;
    const int pbase = wn >> 4;

    float acc[2][4][4] = {};
    #pragma unroll
    for (int kc = 0; kc < 8; ++kc) {
        uint32_t AH[2][4], AL[2][4];
        #pragma unroll
        for (int mi = 0; mi < 2; ++mi) {
            ldm4(AH[mi], aoffH[mi] + kc*32);
            ldm4(AL[mi], aoffL[mi] + kc*32);
        }
        #pragma unroll
        for (int p4 = 0; p4 < 2; ++p4) {
            const int fidx = ((kc*8 + pbase + p4) * 2) * 32;
            const uint4 bh = fw[fidx];
            const uint4 bl = fw[fidx + 32];
            #pragma unroll
            for (int ns = 0; ns < 2; ++ns) {
                const int ni = p4*2 + ns;
                const uint32_t h0 = ns ? bh.z : bh.x, h1 = ns ? bh.w : bh.y;
                const uint32_t l0 = ns ? bl.z : bl.x, l1 = ns ? bl.w : bl.y;
                #pragma unroll
                for (int mi = 0; mi < 2; ++mi) {
                    mma_bf16(acc[mi][ni], AH[mi], h0, h1);
                    mma_bf16(acc[mi][ni], AH[mi], l0, l1);
                    mma_bf16(acc[mi][ni], AL[mi], h0, h1);
                }
            }
        }
    }
    __syncthreads();

    float* stagef = mixbuf;   // reuse as [64][132]
    #pragma unroll
    for (int mi = 0; mi < 2; ++mi)
        #pragma unroll
        for (int ni = 0; ni < 4; ++ni) {
            const int m0 = wm + mi*16 + (lane >> 2);
            const int n  = wn + ni*8 + (lane & 3)*2;
            const float b0 = __ldg(bout + n), b1 = __ldg(bout + n + 1);
            stagef[ m0   *132 + n    ] = acc[mi][ni][0] + b0;
            stagef[ m0   *132 + n + 1] = acc[mi][ni][1] + b1;
            stagef[(m0+8)*132 + n    ] = acc[mi][ni][2] + b0;
            stagef[(m0+8)*132 + n + 1] = acc[mi][ni][3] + b1;
        }
    __syncthreads();

    #pragma unroll
    for (int it = 0; it < 8; ++it) {
        const int idx = it * 256 + tid;
        const int row = idx >> 5, c4 = idx & 31;
        float4 v;
        v.x = stagef[row*132 + c4*4 + 0];
        v.y = stagef[row*132 + c4*4 + 1];
        v.z = stagef[row*132 + c4*4 + 2];
        v.w = stagef[row*132 + c4*4 + 3];
        *reinterpret_cast<float4*>(
            out + ((size_t)(ibase + row)*512 + j)*DD + c4*4) = v;
    }
}

// ---------------------------------------------------------------------------
extern "C" void kernel_launch(void* const* d_in, const int* in_sizes, int n_in,
                              void* d_out, int out_size)
{
    const float* x    = (const float*)d_in[0];
    const float* mskp = (const float*)d_in[1];
    const float* nsc  = (const float*)d_in[2];
    const float* nbi  = (const float*)d_in[3];
    const float* Wl   = (const float*)d_in[4];
    const float* bl   = (const float*)d_in[5];
    const float* Wr   = (const float*)d_in[6];
    const float* br   = (const float*)d_in[7];
    const float* Wlg  = (const float*)d_in[8];
    const float* blg  = (const float*)d_in[9];
    const float* Wrg  = (const float*)d_in[10];
    const float* brg  = (const float*)d_in[11];
    const float* Wog  = (const float*)d_in[12];
    const float* bog  = (const float*)d_in[13];
    const float* gs   = (const float*)d_in[14];
    const float* gb   = (const float*)d_in[15];
    const float* Wout = (const float*)d_in[16];
    const float* bout = (const float*)d_in[17];
    float* out = (float*)d_out;

    cudaFuncSetAttribute(einsum_mma_kernel,
                         cudaFuncAttributeMaxDynamicSharedMemorySize, E2_SMEM);
    cudaFuncSetAttribute(ln_proj_mma_kernel,
                         cudaFuncAttributeMaxDynamicSharedMemorySize, K1_SMEM);
    cudaFuncSetAttribute(out_mma_kernel,
                         cudaFuncAttributeMaxDynamicSharedMemorySize, O_SMEM);

    wprep_kernel<<<6, 256>>>(Wlg, Wl, Wrg, Wr, Wog, Wout);
    ln_proj_mma_kernel<<<4096, 256, K1_SMEM>>>(x, mskp, nsc, nbi,
                                               bl, br, blg, brg, bog);
    einsum_mma_kernel<<<dim3(32, 128), 256, E2_SMEM>>>();
    out_mma_kernel<<<4096, 256, O_SMEM>>>(gs, gb, bout, out);
}